// round 2
// baseline (speedup 1.0000x reference)
#include <cuda_runtime.h>

#define NN   100000
#define NE   3200000
#define FIN  256
#define HC   64      // H1*C1
#define NH   8
#define NCL  41
#define NCLP 44      // padded to 16B multiple (44*4=176)

// ---------------- scratch (static device globals; no runtime alloc) ----------
__device__ __align__(256) float h1g[NN * HC];     // layer1 features, later ELU output
__device__ __align__(256) float s1g[NN * NH];
__device__ __align__(256) float d1g[NN * NH];
__device__ __align__(256) float z1g[NN * NH];
__device__ __align__(256) float acc1g[NN * HC];
__device__ __align__(256) float h2g[NN * NCLP];
__device__ __align__(256) float s2g[NN];
__device__ __align__(256) float d2g[NN];
__device__ __align__(256) float z2g[NN];
__device__ __align__(256) float acc2g[NN * NCLP];

__device__ __forceinline__ float lrelu(float x) { return x > 0.f ? x : 0.2f * x; }

// vector reduction (sm_90+): one L2 transaction for 4 floats
__device__ __forceinline__ void red4(float* p, float a, float b, float c, float d) {
    asm volatile("red.global.add.v4.f32 [%0], {%1,%2,%3,%4};"
                 :: "l"(p), "f"(a), "f"(b), "f"(c), "f"(d) : "memory");
}

// ---------------- GEMM1: h1 = x[NN,256] @ W1[256,64] -------------------------
// 64x64 tile per block, BK=16, 256 threads, 4x4 micro-tile per thread.
__global__ void gemm1_kernel(const float* __restrict__ x, const float* __restrict__ W) {
    __shared__ float xs[64][17];
    __shared__ float ws[16][64];
    int t    = threadIdx.x;
    int row0 = blockIdx.x * 64;
    int tx   = t & 15;        // col group (4 cols)
    int ty   = t >> 4;        // row group (4 rows)

    float acc[4][4];
#pragma unroll
    for (int i = 0; i < 4; i++)
#pragma unroll
        for (int j = 0; j < 4; j++) acc[i][j] = 0.f;

    int lr = t >> 2;           // 0..63 : x-tile row this thread loads
    int lc = (t & 3) << 2;     // 0,4,8,12
    int gr = row0 + lr;

    for (int k0 = 0; k0 < FIN; k0 += 16) {
        float4 xv = make_float4(0.f, 0.f, 0.f, 0.f);
        if (gr < NN) xv = __ldg((const float4*)(x + gr * FIN + k0 + lc));
        xs[lr][lc] = xv.x; xs[lr][lc + 1] = xv.y; xs[lr][lc + 2] = xv.z; xs[lr][lc + 3] = xv.w;

        float4 wv = __ldg((const float4*)(W + (k0 + ty) * HC) + tx);
        *(float4*)&ws[ty][tx << 2] = wv;
        __syncthreads();
#pragma unroll
        for (int kk = 0; kk < 16; kk++) {
            float4 b = *(const float4*)&ws[kk][tx << 2];
            float a0 = xs[(ty << 2) + 0][kk];
            float a1 = xs[(ty << 2) + 1][kk];
            float a2 = xs[(ty << 2) + 2][kk];
            float a3 = xs[(ty << 2) + 3][kk];
            acc[0][0] += a0 * b.x; acc[0][1] += a0 * b.y; acc[0][2] += a0 * b.z; acc[0][3] += a0 * b.w;
            acc[1][0] += a1 * b.x; acc[1][1] += a1 * b.y; acc[1][2] += a1 * b.z; acc[1][3] += a1 * b.w;
            acc[2][0] += a2 * b.x; acc[2][1] += a2 * b.y; acc[2][2] += a2 * b.z; acc[2][3] += a2 * b.w;
            acc[3][0] += a3 * b.x; acc[3][1] += a3 * b.y; acc[3][2] += a3 * b.z; acc[3][3] += a3 * b.w;
        }
        __syncthreads();
    }
#pragma unroll
    for (int i = 0; i < 4; i++) {
        int gr2 = row0 + (ty << 2) + i;
        if (gr2 < NN)
            *(float4*)(h1g + gr2 * HC + (tx << 2)) =
                make_float4(acc[i][0], acc[i][1], acc[i][2], acc[i][3]);
    }
}

// ---------------- node1: attention coefficients + self-loop init -------------
// one thread per (node, head). writes s1,d1; z1 = w_self; acc1 = w_self * h.
__global__ void node1_kernel(const float* __restrict__ a_src, const float* __restrict__ a_dst) {
    int idx = blockIdx.x * blockDim.x + threadIdx.x;
    if (idx >= NN * NH) return;
    int h = idx & 7;
    const float4* hp = (const float4*)(h1g + idx * 8);  // i*64 + h*8 == idx*8
    float4 a = hp[0], b = hp[1];
    const float4* asp = (const float4*)(a_src + h * 8);
    const float4* adp = (const float4*)(a_dst + h * 8);
    float4 s0 = __ldg(asp), s1 = __ldg(asp + 1);
    float4 t0 = __ldg(adp), t1 = __ldg(adp + 1);
    float s = a.x * s0.x + a.y * s0.y + a.z * s0.z + a.w * s0.w +
              b.x * s1.x + b.y * s1.y + b.z * s1.z + b.w * s1.w;
    float d = a.x * t0.x + a.y * t0.y + a.z * t0.z + a.w * t0.w +
              b.x * t1.x + b.y * t1.y + b.z * t1.z + b.w * t1.w;
    s1g[idx] = s;
    d1g[idx] = d;
    float w = __expf(lrelu(s + d));   // self loop: src==dst
    z1g[idx] = w;
    float4* ap = (float4*)(acc1g + idx * 8);
    ap[0] = make_float4(w * a.x, w * a.y, w * a.z, w * a.w);
    ap[1] = make_float4(w * b.x, w * b.y, w * b.z, w * b.w);
}

// ---------------- edge1: 8 threads per edge (one per head) -------------------
__global__ void edge1_kernel(const int* __restrict__ ei) {
    int tid = blockIdx.x * 256 + threadIdx.x;
    int e = tid >> 3;
    if (e >= NE) return;
    int j = tid & 7;
    int src = __ldg(ei + e);
    int dst = __ldg(ei + NE + e);
    float s = __ldg(s1g + src * 8 + j) + __ldg(d1g + dst * 8 + j);
    float w = __expf(lrelu(s));
    atomicAdd(z1g + dst * 8 + j, w);
    const float4* hp = (const float4*)(h1g + src * 64 + j * 8);
    float4 a = __ldg(hp), b = __ldg(hp + 1);
    float* ap = acc1g + dst * 64 + j * 8;
    red4(ap,     w * a.x, w * a.y, w * a.z, w * a.w);
    red4(ap + 4, w * b.x, w * b.y, w * b.z, w * b.w);
}

// ---------------- epi1: normalize + bias + ELU, overwrite h1 -----------------
__global__ void epi1_kernel(const float* __restrict__ b1) {
    int idx = blockIdx.x * blockDim.x + threadIdx.x;
    if (idx >= NN * HC) return;
    int i  = idx >> 6;
    int hc = idx & 63;
    float z = z1g[(i << 3) + (hc >> 3)] + 1e-16f;
    float v = acc1g[idx] / z + __ldg(b1 + hc);
    h1g[idx] = v > 0.f ? v : expm1f(v);
}

// ---------------- gemm2 + node2 init: one block (64 thr) per node ------------
__global__ void gemm2_kernel(const float* __restrict__ W2, const float* __restrict__ a_s,
                             const float* __restrict__ a_d) {
    __shared__ float hs[64];
    __shared__ float rs[64];
    __shared__ float wsh;
    int i = blockIdx.x;
    int t = threadIdx.x;
    hs[t] = h1g[i * 64 + t];
    __syncthreads();
    float acc = 0.f;
    if (t < NCL) {
#pragma unroll 8
        for (int k = 0; k < 64; k++) acc += hs[k] * __ldg(W2 + k * NCL + t);
        h2g[i * NCLP + t] = acc;
    }
    float p = (t < NCL) ? acc * __ldg(a_s + t) : 0.f;
    float q = (t < NCL) ? acc * __ldg(a_d + t) : 0.f;
    rs[t] = p;
    __syncthreads();
    float sv = 0.f;
    if (t < 32) {
        float v = rs[t] + rs[t + 32];
#pragma unroll
        for (int o = 16; o; o >>= 1) v += __shfl_xor_sync(0xffffffffu, v, o);
        sv = v;
    }
    __syncthreads();
    rs[t] = q;
    __syncthreads();
    float dv = 0.f;
    if (t < 32) {
        float v = rs[t] + rs[t + 32];
#pragma unroll
        for (int o = 16; o; o >>= 1) v += __shfl_xor_sync(0xffffffffu, v, o);
        dv = v;
    }
    if (t == 0) {
        s2g[i] = sv;
        d2g[i] = dv;
        float w = __expf(lrelu(sv + dv));   // self loop
        z2g[i] = w;
        wsh = w;
    }
    __syncthreads();
    if (t < NCL) acc2g[i * NCLP + t] = wsh * acc;
}

// ---------------- edge2: 16 threads per edge ---------------------------------
__global__ void edge2_kernel(const int* __restrict__ ei) {
    int tid = blockIdx.x * 256 + threadIdx.x;
    int e = tid >> 4;
    if (e >= NE) return;
    int j = tid & 15;
    int src = __ldg(ei + e);
    int dst = __ldg(ei + NE + e);
    float w = __expf(lrelu(__ldg(s2g + src) + __ldg(d2g + dst)));
    if (j < 10) {
        float4 v = __ldg((const float4*)(h2g + src * NCLP) + j);
        red4(acc2g + dst * NCLP + 4 * j, w * v.x, w * v.y, w * v.z, w * v.w);
    } else if (j == 10) {
        atomicAdd(acc2g + dst * NCLP + 40, w * __ldg(h2g + src * NCLP + 40));
    } else if (j == 11) {
        atomicAdd(z2g + dst, w);
    }
}

// ---------------- epi2: normalize + bias + log_softmax, warp per node --------
__global__ void epi2_kernel(const float* __restrict__ b2, float* __restrict__ out) {
    int gw = (blockIdx.x * blockDim.x + threadIdx.x) >> 5;
    if (gw >= NN) return;
    int l = threadIdx.x & 31;
    float z = z2g[gw] + 1e-16f;
    float v0 = acc2g[gw * NCLP + l] / z + __ldg(b2 + l);
    float v1 = -1e30f;
    if (l < 9) v1 = acc2g[gw * NCLP + 32 + l] / z + __ldg(b2 + 32 + l);
    float m = fmaxf(v0, v1);
#pragma unroll
    for (int o = 16; o; o >>= 1) m = fmaxf(m, __shfl_xor_sync(0xffffffffu, m, o));
    float se = __expf(v0 - m) + ((l < 9) ? __expf(v1 - m) : 0.f);
#pragma unroll
    for (int o = 16; o; o >>= 1) se += __shfl_xor_sync(0xffffffffu, se, o);
    float ls = m + logf(se);
    out[gw * NCL + l] = v0 - ls;
    if (l < 9) out[gw * NCL + 32 + l] = v1 - ls;
}

// ---------------- launch ------------------------------------------------------
extern "C" void kernel_launch(void* const* d_in, const int* in_sizes, int n_in,
                              void* d_out, int out_size) {
    const float* x      = (const float*)d_in[0];
    const int*   ei     = (const int*)d_in[1];
    const float* W1     = (const float*)d_in[2];
    const float* a_src1 = (const float*)d_in[3];
    const float* a_dst1 = (const float*)d_in[4];
    const float* b1     = (const float*)d_in[5];
    const float* W2     = (const float*)d_in[6];
    const float* a_src2 = (const float*)d_in[7];
    const float* a_dst2 = (const float*)d_in[8];
    const float* b2     = (const float*)d_in[9];
    float*       out    = (float*)d_out;

    gemm1_kernel<<<(NN + 63) / 64, 256>>>(x, W1);
    node1_kernel<<<(NN * NH + 255) / 256, 256>>>(a_src1, a_dst1);
    edge1_kernel<<<(NE * 8 + 255) / 256, 256>>>(ei);
    epi1_kernel<<<(NN * HC + 255) / 256, 256>>>(b1);
    gemm2_kernel<<<NN, 64>>>(W2, a_src2, a_dst2);
    edge2_kernel<<<(NE * 16 + 255) / 256, 256>>>(ei);
    epi2_kernel<<<(NN * 32 + 255) / 256, 256>>>(b2, out);
}

// round 3
// speedup vs baseline: 1.0870x; 1.0870x over previous
#include <cuda_runtime.h>
#include <cuda_fp16.h>

#define NN   100000
#define NE   3200000
#define FIN  256
#define HC   64      // H1*C1
#define NH   8
#define NCL  41
#define NCLP 44      // acc2 row stride (floats), 176B = 16B multiple
#define H2S  48      // h2h row stride (halves), 96B = 16B multiple

// ---------------- scratch (static device globals; no runtime alloc) ----------
__device__ __align__(256) float  h1g[NN * HC];     // layer1 pre-act (fp32, for node1), then ELU out
__device__ __align__(256) __half h1h[NN * HC];     // fp16 copy for edge1 gathers
__device__ __align__(256) float  s1g[NN * NH];
__device__ __align__(256) float  d1g[NN * NH];
__device__ __align__(256) float  z1g[NN * NH];
__device__ __align__(256) float  acc1g[NN * HC];
__device__ __align__(256) __half h2h[NN * H2S];    // fp16 layer2 features for edge2 gathers
__device__ __align__(256) float  s2g[NN];
__device__ __align__(256) float  d2g[NN];
__device__ __align__(256) float  z2g[NN];
__device__ __align__(256) float  acc2g[NN * NCLP];

__device__ __forceinline__ float lrelu(float x) { return x > 0.f ? x : 0.2f * x; }

// vector reduction (sm_90+): one L2 transaction for 4 floats
__device__ __forceinline__ void red4(float* p, float a, float b, float c, float d) {
    asm volatile("red.global.add.v4.f32 [%0], {%1,%2,%3,%4};"
                 :: "l"(p), "f"(a), "f"(b), "f"(c), "f"(d) : "memory");
}

// ---------------- GEMM1: h1 = x[NN,256] @ W1[256,64] -------------------------
__global__ void gemm1_kernel(const float* __restrict__ x, const float* __restrict__ W) {
    __shared__ float xs[64][17];
    __shared__ float ws[16][64];
    int t    = threadIdx.x;
    int row0 = blockIdx.x * 64;
    int tx   = t & 15;
    int ty   = t >> 4;

    float acc[4][4];
#pragma unroll
    for (int i = 0; i < 4; i++)
#pragma unroll
        for (int j = 0; j < 4; j++) acc[i][j] = 0.f;

    int lr = t >> 2;
    int lc = (t & 3) << 2;
    int gr = row0 + lr;

    for (int k0 = 0; k0 < FIN; k0 += 16) {
        float4 xv = make_float4(0.f, 0.f, 0.f, 0.f);
        if (gr < NN) xv = __ldg((const float4*)(x + gr * FIN + k0 + lc));
        xs[lr][lc] = xv.x; xs[lr][lc + 1] = xv.y; xs[lr][lc + 2] = xv.z; xs[lr][lc + 3] = xv.w;

        float4 wv = __ldg((const float4*)(W + (k0 + ty) * HC) + tx);
        *(float4*)&ws[ty][tx << 2] = wv;
        __syncthreads();
#pragma unroll
        for (int kk = 0; kk < 16; kk++) {
            float4 b = *(const float4*)&ws[kk][tx << 2];
            float a0 = xs[(ty << 2) + 0][kk];
            float a1 = xs[(ty << 2) + 1][kk];
            float a2 = xs[(ty << 2) + 2][kk];
            float a3 = xs[(ty << 2) + 3][kk];
            acc[0][0] += a0 * b.x; acc[0][1] += a0 * b.y; acc[0][2] += a0 * b.z; acc[0][3] += a0 * b.w;
            acc[1][0] += a1 * b.x; acc[1][1] += a1 * b.y; acc[1][2] += a1 * b.z; acc[1][3] += a1 * b.w;
            acc[2][0] += a2 * b.x; acc[2][1] += a2 * b.y; acc[2][2] += a2 * b.z; acc[2][3] += a2 * b.w;
            acc[3][0] += a3 * b.x; acc[3][1] += a3 * b.y; acc[3][2] += a3 * b.z; acc[3][3] += a3 * b.w;
        }
        __syncthreads();
    }
#pragma unroll
    for (int i = 0; i < 4; i++) {
        int gr2 = row0 + (ty << 2) + i;
        if (gr2 < NN) {
            *(float4*)(h1g + gr2 * HC + (tx << 2)) =
                make_float4(acc[i][0], acc[i][1], acc[i][2], acc[i][3]);
            __half2 p0 = __floats2half2_rn(acc[i][0], acc[i][1]);
            __half2 p1 = __floats2half2_rn(acc[i][2], acc[i][3]);
            *(__half2*)(h1h + gr2 * HC + (tx << 2))     = p0;
            *(__half2*)(h1h + gr2 * HC + (tx << 2) + 2) = p1;
        }
    }
}

// ---------------- node1: attention coefficients + self-loop init -------------
__global__ void node1_kernel(const float* __restrict__ a_src, const float* __restrict__ a_dst) {
    int idx = blockIdx.x * blockDim.x + threadIdx.x;
    if (idx >= NN * NH) return;
    int h = idx & 7;
    const float4* hp = (const float4*)(h1g + idx * 8);
    float4 a = hp[0], b = hp[1];
    const float4* asp = (const float4*)(a_src + h * 8);
    const float4* adp = (const float4*)(a_dst + h * 8);
    float4 s0 = __ldg(asp), s1 = __ldg(asp + 1);
    float4 t0 = __ldg(adp), t1 = __ldg(adp + 1);
    float s = a.x * s0.x + a.y * s0.y + a.z * s0.z + a.w * s0.w +
              b.x * s1.x + b.y * s1.y + b.z * s1.z + b.w * s1.w;
    float d = a.x * t0.x + a.y * t0.y + a.z * t0.z + a.w * t0.w +
              b.x * t1.x + b.y * t1.y + b.z * t1.z + b.w * t1.w;
    s1g[idx] = s;
    d1g[idx] = d;
    float w = __expf(lrelu(s + d));   // self loop: src==dst
    z1g[idx] = w;
    float4* ap = (float4*)(acc1g + idx * 8);
    ap[0] = make_float4(w * a.x, w * a.y, w * a.z, w * a.w);
    ap[1] = make_float4(w * b.x, w * b.y, w * b.z, w * b.w);
}

// ---------------- edge1: 8 lanes per edge (one per head) ---------------------
// grid is exactly NE*8/256 blocks (no tail) -> full warps, shuffles safe.
__global__ void edge1_kernel(const int* __restrict__ ei) {
    int tid  = blockIdx.x * 256 + threadIdx.x;
    int e    = tid >> 3;
    int j    = tid & 7;                 // head
    int lane = threadIdx.x & 31;
    int src = __ldg(ei + e);
    int dst = __ldg(ei + NE + e);
    float s = __ldg(s1g + src * 8 + j) + __ldg(d1g + dst * 8 + j);
    float w = __expf(lrelu(s));

    // z1 reduction: gather 4 lanes' w, one red4 per 4 lanes (2 per edge)
    int base4 = lane & ~3;
    float w0 = __shfl_sync(0xffffffffu, w, base4);
    float w1 = __shfl_sync(0xffffffffu, w, base4 + 1);
    float w2 = __shfl_sync(0xffffffffu, w, base4 + 2);
    float w3 = __shfl_sync(0xffffffffu, w, base4 + 3);
    if ((lane & 3) == 0)
        red4(z1g + dst * 8 + (j & 4), w0, w1, w2, w3);

    // fp16 gather of this head's 8 channels (16B)
    uint4 hv = __ldg((const uint4*)(h1h + src * 64 + j * 8));
    const __half2* hp = (const __half2*)&hv;
    float2 f0 = __half22float2(hp[0]);
    float2 f1 = __half22float2(hp[1]);
    float2 f2 = __half22float2(hp[2]);
    float2 f3 = __half22float2(hp[3]);
    float* ap = acc1g + dst * 64 + j * 8;
    red4(ap,     w * f0.x, w * f0.y, w * f1.x, w * f1.y);
    red4(ap + 4, w * f2.x, w * f2.y, w * f3.x, w * f3.y);
}

// ---------------- epi1: normalize + bias + ELU, overwrite h1 -----------------
__global__ void epi1_kernel(const float* __restrict__ b1) {
    int idx = blockIdx.x * blockDim.x + threadIdx.x;
    if (idx >= NN * HC) return;
    int i  = idx >> 6;
    int hc = idx & 63;
    float z = z1g[(i << 3) + (hc >> 3)] + 1e-16f;
    float v = acc1g[idx] / z + __ldg(b1 + hc);
    h1g[idx] = v > 0.f ? v : expm1f(v);
}

// ---------------- gemm2 + node2 init: one block (64 thr) per node ------------
__global__ void gemm2_kernel(const float* __restrict__ W2, const float* __restrict__ a_s,
                             const float* __restrict__ a_d) {
    __shared__ float hs[64];
    __shared__ float rs[64];
    __shared__ float wsh;
    int i = blockIdx.x;
    int t = threadIdx.x;
    hs[t] = h1g[i * 64 + t];
    __syncthreads();
    float acc = 0.f;
    if (t < NCL) {
#pragma unroll 8
        for (int k = 0; k < 64; k++) acc += hs[k] * __ldg(W2 + k * NCL + t);
        h2h[i * H2S + t] = __float2half(acc);
    }
    float p = (t < NCL) ? acc * __ldg(a_s + t) : 0.f;
    float q = (t < NCL) ? acc * __ldg(a_d + t) : 0.f;
    rs[t] = p;
    __syncthreads();
    float sv = 0.f;
    if (t < 32) {
        float v = rs[t] + rs[t + 32];
#pragma unroll
        for (int o = 16; o; o >>= 1) v += __shfl_xor_sync(0xffffffffu, v, o);
        sv = v;
    }
    __syncthreads();
    rs[t] = q;
    __syncthreads();
    float dv = 0.f;
    if (t < 32) {
        float v = rs[t] + rs[t + 32];
#pragma unroll
        for (int o = 16; o; o >>= 1) v += __shfl_xor_sync(0xffffffffu, v, o);
        dv = v;
    }
    if (t == 0) {
        s2g[i] = sv;
        d2g[i] = dv;
        float w = __expf(lrelu(sv + dv));   // self loop
        z2g[i] = w;
        wsh = w;
    }
    __syncthreads();
    if (t < NCL) acc2g[i * NCLP + t] = wsh * acc;
}

// ---------------- edge2: 8 lanes per edge -------------------------------------
// lanes 0..4: 8 channels each (fp16 gather 16B + 2x red4); lane 5: ch40; lane 6: z
__global__ void edge2_kernel(const int* __restrict__ ei) {
    int tid = blockIdx.x * 256 + threadIdx.x;
    int e = tid >> 3;
    int j = tid & 7;
    int src = __ldg(ei + e);
    int dst = __ldg(ei + NE + e);
    float w = __expf(lrelu(__ldg(s2g + src) + __ldg(d2g + dst)));
    if (j < 5) {
        uint4 hv = __ldg((const uint4*)(h2h + src * H2S + j * 8));
        const __half2* hp = (const __half2*)&hv;
        float2 f0 = __half22float2(hp[0]);
        float2 f1 = __half22float2(hp[1]);
        float2 f2 = __half22float2(hp[2]);
        float2 f3 = __half22float2(hp[3]);
        float* ap = acc2g + dst * NCLP + j * 8;
        red4(ap,     w * f0.x, w * f0.y, w * f1.x, w * f1.y);
        red4(ap + 4, w * f2.x, w * f2.y, w * f3.x, w * f3.y);
    } else if (j == 5) {
        float v = __half2float(__ldg(h2h + src * H2S + 40));
        atomicAdd(acc2g + dst * NCLP + 40, w * v);
    } else if (j == 6) {
        atomicAdd(z2g + dst, w);
    }
}

// ---------------- epi2: normalize + bias + log_softmax, warp per node --------
__global__ void epi2_kernel(const float* __restrict__ b2, float* __restrict__ out) {
    int gw = (blockIdx.x * blockDim.x + threadIdx.x) >> 5;
    if (gw >= NN) return;
    int l = threadIdx.x & 31;
    float z = z2g[gw] + 1e-16f;
    float v0 = acc2g[gw * NCLP + l] / z + __ldg(b2 + l);
    float v1 = -1e30f;
    if (l < 9) v1 = acc2g[gw * NCLP + 32 + l] / z + __ldg(b2 + 32 + l);
    float m = fmaxf(v0, v1);
#pragma unroll
    for (int o = 16; o; o >>= 1) m = fmaxf(m, __shfl_xor_sync(0xffffffffu, m, o));
    float se = __expf(v0 - m) + ((l < 9) ? __expf(v1 - m) : 0.f);
#pragma unroll
    for (int o = 16; o; o >>= 1) se += __shfl_xor_sync(0xffffffffu, se, o);
    float ls = m + logf(se);
    out[gw * NCL + l] = v0 - ls;
    if (l < 9) out[gw * NCL + 32 + l] = v1 - ls;
}

// ---------------- launch ------------------------------------------------------
extern "C" void kernel_launch(void* const* d_in, const int* in_sizes, int n_in,
                              void* d_out, int out_size) {
    const float* x      = (const float*)d_in[0];
    const int*   ei     = (const int*)d_in[1];
    const float* W1     = (const float*)d_in[2];
    const float* a_src1 = (const float*)d_in[3];
    const float* a_dst1 = (const float*)d_in[4];
    const float* b1     = (const float*)d_in[5];
    const float* W2     = (const float*)d_in[6];
    const float* a_src2 = (const float*)d_in[7];
    const float* a_dst2 = (const float*)d_in[8];
    const float* b2     = (const float*)d_in[9];
    float*       out    = (float*)d_out;

    gemm1_kernel<<<(NN + 63) / 64, 256>>>(x, W1);
    node1_kernel<<<(NN * NH + 255) / 256, 256>>>(a_src1, a_dst1);
    edge1_kernel<<<(NE * 8) / 256, 256>>>(ei);          // exact division, no tail
    epi1_kernel<<<(NN * HC + 255) / 256, 256>>>(b1);
    gemm2_kernel<<<NN, 64>>>(W2, a_src2, a_dst2);
    edge2_kernel<<<(NE * 8) / 256, 256>>>(ei);          // exact division, no tail
    epi2_kernel<<<(NN * 32 + 255) / 256, 256>>>(b2, out);
}

// round 4
// speedup vs baseline: 1.3969x; 1.2851x over previous
#include <cuda_runtime.h>
#include <cuda_fp16.h>

#define NN   100000
#define NE   3200000
#define FIN  256
#define HC   64      // H1*C1
#define NH   8
#define NCL  41
#define H2S  48      // h2h row stride in halves (96B); channels 41..47 stay zero

// ---------------- scratch (static device globals; no runtime alloc) ----------
__device__ __align__(256) float  h1g[NN * HC];     // gemm1 out (fp32), then ELU out (agg1)
__device__ __align__(256) __half h1h[NN * HC];     // fp16 copy of gemm1 out for gathers
__device__ __align__(256) float  s1g[NN * NH];
__device__ __align__(256) float  d1g[NN * NH];
__device__ __align__(256) __half h2h[NN * H2S];    // fp16 layer2 features
__device__ __align__(256) float  s2g[NN];
__device__ __align__(256) float  d2g[NN];
__device__ __align__(256) int    cntg[NN];
__device__ __align__(256) int    offg[NN + 1];
__device__ __align__(256) int    curg[NN];
__device__ __align__(256) int    csrg[NE];

__device__ __forceinline__ float lrelu(float x) { return fmaxf(x, 0.2f * x); }

// ---------------- GEMM1: h1 = x[NN,256] @ W1[256,64] -------------------------
__global__ void gemm1_kernel(const float* __restrict__ x, const float* __restrict__ W) {
    __shared__ float xs[64][17];
    __shared__ float ws[16][64];
    int t    = threadIdx.x;
    int row0 = blockIdx.x * 64;
    int tx   = t & 15;
    int ty   = t >> 4;

    float acc[4][4];
#pragma unroll
    for (int i = 0; i < 4; i++)
#pragma unroll
        for (int j = 0; j < 4; j++) acc[i][j] = 0.f;

    int lr = t >> 2;
    int lc = (t & 3) << 2;
    int gr = row0 + lr;

    for (int k0 = 0; k0 < FIN; k0 += 16) {
        float4 xv = make_float4(0.f, 0.f, 0.f, 0.f);
        if (gr < NN) xv = __ldg((const float4*)(x + gr * FIN + k0 + lc));
        xs[lr][lc] = xv.x; xs[lr][lc + 1] = xv.y; xs[lr][lc + 2] = xv.z; xs[lr][lc + 3] = xv.w;

        float4 wv = __ldg((const float4*)(W + (k0 + ty) * HC) + tx);
        *(float4*)&ws[ty][tx << 2] = wv;
        __syncthreads();
#pragma unroll
        for (int kk = 0; kk < 16; kk++) {
            float4 b = *(const float4*)&ws[kk][tx << 2];
            float a0 = xs[(ty << 2) + 0][kk];
            float a1 = xs[(ty << 2) + 1][kk];
            float a2 = xs[(ty << 2) + 2][kk];
            float a3 = xs[(ty << 2) + 3][kk];
            acc[0][0] += a0 * b.x; acc[0][1] += a0 * b.y; acc[0][2] += a0 * b.z; acc[0][3] += a0 * b.w;
            acc[1][0] += a1 * b.x; acc[1][1] += a1 * b.y; acc[1][2] += a1 * b.z; acc[1][3] += a1 * b.w;
            acc[2][0] += a2 * b.x; acc[2][1] += a2 * b.y; acc[2][2] += a2 * b.z; acc[2][3] += a2 * b.w;
            acc[3][0] += a3 * b.x; acc[3][1] += a3 * b.y; acc[3][2] += a3 * b.z; acc[3][3] += a3 * b.w;
        }
        __syncthreads();
    }
#pragma unroll
    for (int i = 0; i < 4; i++) {
        int gr2 = row0 + (ty << 2) + i;
        if (gr2 < NN) {
            *(float4*)(h1g + gr2 * HC + (tx << 2)) =
                make_float4(acc[i][0], acc[i][1], acc[i][2], acc[i][3]);
            __half2 p0 = __floats2half2_rn(acc[i][0], acc[i][1]);
            __half2 p1 = __floats2half2_rn(acc[i][2], acc[i][3]);
            *(__half2*)(h1h + gr2 * HC + (tx << 2))     = p0;
            *(__half2*)(h1h + gr2 * HC + (tx << 2) + 2) = p1;
        }
    }
}

// ---------------- node1: attention coefficients only -------------------------
__global__ void node1_kernel(const float* __restrict__ a_src, const float* __restrict__ a_dst) {
    int idx = blockIdx.x * blockDim.x + threadIdx.x;
    if (idx >= NN * NH) return;
    int h = idx & 7;
    const float4* hp = (const float4*)(h1g + idx * 8);
    float4 a = hp[0], b = hp[1];
    const float4* asp = (const float4*)(a_src + h * 8);
    const float4* adp = (const float4*)(a_dst + h * 8);
    float4 s0 = __ldg(asp), s1 = __ldg(asp + 1);
    float4 t0 = __ldg(adp), t1 = __ldg(adp + 1);
    float s = a.x * s0.x + a.y * s0.y + a.z * s0.z + a.w * s0.w +
              b.x * s1.x + b.y * s1.y + b.z * s1.z + b.w * s1.w;
    float d = a.x * t0.x + a.y * t0.y + a.z * t0.z + a.w * t0.w +
              b.x * t1.x + b.y * t1.y + b.z * t1.z + b.w * t1.w;
    s1g[idx] = s;
    d1g[idx] = d;
}

// ---------------- CSR build ---------------------------------------------------
__global__ void zero_kernel() {
    int i = blockIdx.x * blockDim.x + threadIdx.x;
    if (i < NN) cntg[i] = 0;
}

__global__ void hist_kernel(const int* __restrict__ ei) {
    int e = blockIdx.x * blockDim.x + threadIdx.x;
    if (e < NE) atomicAdd(cntg + __ldg(ei + NE + e), 1);
}

// single-block exclusive scan of cntg -> offg (+ copy to curg), 4 elems/thread
__global__ void scan_kernel() {
    __shared__ int wsum[32];
    __shared__ int carry_s;
    int t = threadIdx.x, lane = t & 31, wid = t >> 5;
    if (t == 0) carry_s = 0;
    __syncthreads();
    for (int base = 0; base < NN; base += 4096) {
        int i0 = base + t * 4;
        int v0 = (i0     < NN) ? cntg[i0]     : 0;
        int v1 = (i0 + 1 < NN) ? cntg[i0 + 1] : 0;
        int v2 = (i0 + 2 < NN) ? cntg[i0 + 2] : 0;
        int v3 = (i0 + 3 < NN) ? cntg[i0 + 3] : 0;
        int tsum = v0 + v1 + v2 + v3;
        int x = tsum;
#pragma unroll
        for (int o = 1; o < 32; o <<= 1) {
            int y = __shfl_up_sync(0xffffffffu, x, o);
            if (lane >= o) x += y;
        }
        if (lane == 31) wsum[wid] = x;
        __syncthreads();
        if (wid == 0) {
            int y = wsum[lane];
#pragma unroll
            for (int o = 1; o < 32; o <<= 1) {
                int z2 = __shfl_up_sync(0xffffffffu, y, o);
                if (lane >= o) y += z2;
            }
            wsum[lane] = y;
        }
        __syncthreads();
        int incl = x + (wid ? wsum[wid - 1] : 0);
        int excl = incl - tsum + carry_s;
        if (i0     < NN) { offg[i0]     = excl;                curg[i0]     = excl; }
        if (i0 + 1 < NN) { offg[i0 + 1] = excl + v0;           curg[i0 + 1] = excl + v0; }
        if (i0 + 2 < NN) { offg[i0 + 2] = excl + v0 + v1;      curg[i0 + 2] = excl + v0 + v1; }
        if (i0 + 3 < NN) { offg[i0 + 3] = excl + v0 + v1 + v2; curg[i0 + 3] = excl + v0 + v1 + v2; }
        __syncthreads();
        if (t == 1023) carry_s += incl;
        __syncthreads();
    }
    if (t == 0) offg[NN] = carry_s;
}

__global__ void scatter_kernel(const int* __restrict__ ei) {
    int e = blockIdx.x * blockDim.x + threadIdx.x;
    if (e >= NE) return;
    int src = __ldg(ei + e);
    int dst = __ldg(ei + NE + e);
    int pos = atomicAdd(curg + dst, 1);
    csrg[pos] = src;
}

// ---------------- agg1: warp per dst, fused normalize+bias+ELU ---------------
// lane l owns channels 2l,2l+1 (head = l>>2)
__global__ void agg1_kernel(const float* __restrict__ b1) {
    int w = blockIdx.x * 8 + (threadIdx.x >> 5);
    if (w >= NN) return;
    int l = threadIdx.x & 31;
    int dst = w;
    float dl = __ldg(d1g + dst * 8 + (l & 7));

    // self loop
    float s8 = __ldg(s1g + dst * 8 + (l & 7));
    float w8 = __expf(lrelu(s8 + dl));
    float ww = __shfl_sync(0xffffffffu, w8, l >> 2);
    unsigned hv = __ldg((const unsigned*)h1h + dst * 32 + l);
    float2 f = __half22float2(*(__half2*)&hv);
    float a0 = ww * f.x, a1 = ww * f.y, z = ww;

    int beg = __ldg(offg + dst), end = __ldg(offg + dst + 1);
    for (int k0 = beg; k0 < end; k0 += 32) {
        int n = end - k0; if (n > 32) n = 32;
        int srcl = __ldg(csrg + k0 + (l < n ? l : n - 1));
#pragma unroll 4
        for (int i = 0; i < n; i++) {
            int src = __shfl_sync(0xffffffffu, srcl, i);
            float se = __ldg(s1g + src * 8 + (l & 7));
            float we8 = __expf(lrelu(se + dl));
            float we = __shfl_sync(0xffffffffu, we8, l >> 2);
            unsigned h = __ldg((const unsigned*)h1h + src * 32 + l);
            float2 g = __half22float2(*(__half2*)&h);
            a0 += we * g.x; a1 += we * g.y; z += we;
        }
    }
    float inv = 1.0f / (z + 1e-16f);
    float v0 = a0 * inv + __ldg(b1 + 2 * l);
    float v1 = a1 * inv + __ldg(b1 + 2 * l + 1);
    v0 = v0 > 0.f ? v0 : expm1f(v0);
    v1 = v1 > 0.f ? v1 : expm1f(v1);
    *(float2*)(h1g + dst * 64 + 2 * l) = make_float2(v0, v1);
}

// ---------------- gemm2: 32 nodes per 256-thread block, W2 in smem -----------
__global__ void gemm2_kernel(const float* __restrict__ W2, const float* __restrict__ a_s,
                             const float* __restrict__ a_d) {
    __shared__ float Ws[64 * 44];
    __shared__ float as_s[44], ad_s[44];
    int t = threadIdx.x;
    for (int idx = t; idx < 64 * NCL; idx += 256) {
        int k = idx / NCL, c = idx % NCL;
        Ws[k * 44 + c] = __ldg(W2 + idx);
    }
    if (t < NCL) { as_s[t] = __ldg(a_s + t); ad_s[t] = __ldg(a_d + t); }
    __syncthreads();
    int wid = t >> 5, l = t & 31;
#pragma unroll
    for (int it = 0; it < 4; it++) {
        int n = blockIdx.x * 32 + wid * 4 + it;
        if (n >= NN) continue;
        float hlo = h1g[n * 64 + l];
        float hhi = h1g[n * 64 + 32 + l];
        float acc0 = 0.f, acc1 = 0.f;   // channels c=l and c=l+32 (latter valid l<9)
#pragma unroll
        for (int k = 0; k < 32; k++) {
            float hk = __shfl_sync(0xffffffffu, hlo, k);
            acc0 += hk * Ws[k * 44 + l];
            if (l < 9) acc1 += hk * Ws[k * 44 + 32 + l];
        }
#pragma unroll
        for (int k = 0; k < 32; k++) {
            float hk = __shfl_sync(0xffffffffu, hhi, k);
            acc0 += hk * Ws[(k + 32) * 44 + l];
            if (l < 9) acc1 += hk * Ws[(k + 32) * 44 + 32 + l];
        }
        // s2/d2 reductions
        float sp = acc0 * as_s[l] + (l < 9 ? acc1 * as_s[32 + l] : 0.f);
        float dp = acc0 * ad_s[l] + (l < 9 ? acc1 * ad_s[32 + l] : 0.f);
#pragma unroll
        for (int o = 16; o; o >>= 1) {
            sp += __shfl_xor_sync(0xffffffffu, sp, o);
            dp += __shfl_xor_sync(0xffffffffu, dp, o);
        }
        if (l == 0) { s2g[n] = sp; d2g[n] = dp; }
        // write fp16 features: lane l<21 writes channels (2l, 2l+1)
        float x0 = __shfl_sync(0xffffffffu, acc0, (2 * l) & 31);
        float y0 = __shfl_sync(0xffffffffu, acc1, (2 * l) & 31);
        float x1 = __shfl_sync(0xffffffffu, acc0, (2 * l + 1) & 31);
        float y1 = __shfl_sync(0xffffffffu, acc1, (2 * l + 1) & 31);
        float e0 = (2 * l     < 32) ? x0 : y0;
        float e1 = (2 * l + 1 < 32) ? x1 : y1;
        if (l < 21) {
            if (l == 20) e1 = 0.f;  // channel 41 pad
            ((__half2*)(h2h + n * H2S))[l] = __floats2half2_rn(e0, e1);
        }
    }
}

// ---------------- agg2: warp per dst, fused log_softmax ----------------------
// lane l owns channels 2l,2l+1 (valid while < 41); h2h pads are zero
__global__ void agg2_kernel(const float* __restrict__ b2, float* __restrict__ out) {
    int w = blockIdx.x * 8 + (threadIdx.x >> 5);
    if (w >= NN) return;
    int l = threadIdx.x & 31;
    int dst = w;
    int li = l < 24 ? l : 23;
    float dv = __ldg(d2g + dst);

    // self loop
    float ws = __expf(lrelu(__ldg(s2g + dst) + dv));
    unsigned hv = __ldg((const unsigned*)h2h + dst * 24 + li);
    float2 f = __half22float2(*(__half2*)&hv);
    float a0 = ws * f.x, a1 = ws * f.y, z = ws;

    int beg = __ldg(offg + dst), end = __ldg(offg + dst + 1);
    for (int k0 = beg; k0 < end; k0 += 32) {
        int n = end - k0; if (n > 32) n = 32;
        int srcl = __ldg(csrg + k0 + (l < n ? l : n - 1));
#pragma unroll 4
        for (int i = 0; i < n; i++) {
            int src = __shfl_sync(0xffffffffu, srcl, i);
            float we = __expf(lrelu(__ldg(s2g + src) + dv));
            unsigned h = __ldg((const unsigned*)h2h + src * 24 + li);
            float2 g = __half22float2(*(__half2*)&h);
            a0 += we * g.x; a1 += we * g.y; z += we;
        }
    }
    float inv = 1.0f / (z + 1e-16f);
    int c0 = 2 * l, c1 = 2 * l + 1;
    float v0 = (c0 < NCL) ? a0 * inv + __ldg(b2 + c0) : -1e30f;
    float v1 = (c1 < NCL) ? a1 * inv + __ldg(b2 + c1) : -1e30f;
    float m = fmaxf(v0, v1);
#pragma unroll
    for (int o = 16; o; o >>= 1) m = fmaxf(m, __shfl_xor_sync(0xffffffffu, m, o));
    float se = ((c0 < NCL) ? __expf(v0 - m) : 0.f) + ((c1 < NCL) ? __expf(v1 - m) : 0.f);
#pragma unroll
    for (int o = 16; o; o >>= 1) se += __shfl_xor_sync(0xffffffffu, se, o);
    float ls = m + logf(se);
    if (c0 < NCL) out[dst * NCL + c0] = v0 - ls;
    if (c1 < NCL) out[dst * NCL + c1] = v1 - ls;
}

// ---------------- launch ------------------------------------------------------
extern "C" void kernel_launch(void* const* d_in, const int* in_sizes, int n_in,
                              void* d_out, int out_size) {
    const float* x      = (const float*)d_in[0];
    const int*   ei     = (const int*)d_in[1];
    const float* W1     = (const float*)d_in[2];
    const float* a_src1 = (const float*)d_in[3];
    const float* a_dst1 = (const float*)d_in[4];
    const float* b1     = (const float*)d_in[5];
    const float* W2     = (const float*)d_in[6];
    const float* a_src2 = (const float*)d_in[7];
    const float* a_dst2 = (const float*)d_in[8];
    const float* b2     = (const float*)d_in[9];
    float*       out    = (float*)d_out;

    gemm1_kernel<<<(NN + 63) / 64, 256>>>(x, W1);
    node1_kernel<<<(NN * NH + 255) / 256, 256>>>(a_src1, a_dst1);

    zero_kernel<<<(NN + 255) / 256, 256>>>();
    hist_kernel<<<NE / 256, 256>>>(ei);
    scan_kernel<<<1, 1024>>>();
    scatter_kernel<<<NE / 256, 256>>>(ei);

    agg1_kernel<<<(NN + 7) / 8, 256>>>(b1);
    gemm2_kernel<<<(NN + 31) / 32, 256>>>(W2, a_src2, a_dst2);
    agg2_kernel<<<(NN + 7) / 8, 256>>>(b2, out);
}

// round 5
// speedup vs baseline: 1.4731x; 1.0545x over previous
#include <cuda_runtime.h>
#include <cuda_fp16.h>

#define NN   100000
#define NE   3200000
#define FIN  256
#define HC   64      // H1*C1
#define NH   8
#define NCL  41
#define H2S  48      // h2h row stride in halves (96B); channels 42..47 stay zero forever

// ---------------- scratch (static device globals; no runtime alloc) ----------
__device__ __align__(256) float  h1g[NN * HC];     // gemm1 out (fp32) for node1
__device__ __align__(256) __half h1h[NN * HC];     // fp16 gemm1 out for agg1 gathers
__device__ __align__(256) __half h1e[NN * HC];     // fp16 ELU output (agg1 -> gemm2)
__device__ __align__(256) float  s1g[NN * NH];
__device__ __align__(256) float  d1g[NN * NH];
__device__ __align__(256) __half h2h[NN * H2S];    // fp16 layer2 features
__device__ __align__(256) float  s2g[NN];
__device__ __align__(256) float  d2g[NN];
__device__ __align__(256) int    cntg[NN];
__device__ __align__(256) int    offg[NN + 1];
__device__ __align__(256) int    curg[NN];
__device__ __align__(256) int    csrg[NE];

__device__ __forceinline__ float lrelu(float x) { return fmaxf(x, 0.2f * x); }

// ---------------- GEMM1: h1 = x[NN,256] @ W1[256,64] -------------------------
__global__ void gemm1_kernel(const float* __restrict__ x, const float* __restrict__ W) {
    __shared__ float xs[64][17];
    __shared__ float ws[16][64];
    int t    = threadIdx.x;
    int row0 = blockIdx.x * 64;
    int tx   = t & 15;
    int ty   = t >> 4;

    float acc[4][4];
#pragma unroll
    for (int i = 0; i < 4; i++)
#pragma unroll
        for (int j = 0; j < 4; j++) acc[i][j] = 0.f;

    int lr = t >> 2;
    int lc = (t & 3) << 2;
    int gr = row0 + lr;

    for (int k0 = 0; k0 < FIN; k0 += 16) {
        float4 xv = make_float4(0.f, 0.f, 0.f, 0.f);
        if (gr < NN) xv = __ldg((const float4*)(x + gr * FIN + k0 + lc));
        xs[lr][lc] = xv.x; xs[lr][lc + 1] = xv.y; xs[lr][lc + 2] = xv.z; xs[lr][lc + 3] = xv.w;

        float4 wv = __ldg((const float4*)(W + (k0 + ty) * HC) + tx);
        *(float4*)&ws[ty][tx << 2] = wv;
        __syncthreads();
#pragma unroll
        for (int kk = 0; kk < 16; kk++) {
            float4 b = *(const float4*)&ws[kk][tx << 2];
            float a0 = xs[(ty << 2) + 0][kk];
            float a1 = xs[(ty << 2) + 1][kk];
            float a2 = xs[(ty << 2) + 2][kk];
            float a3 = xs[(ty << 2) + 3][kk];
            acc[0][0] += a0 * b.x; acc[0][1] += a0 * b.y; acc[0][2] += a0 * b.z; acc[0][3] += a0 * b.w;
            acc[1][0] += a1 * b.x; acc[1][1] += a1 * b.y; acc[1][2] += a1 * b.z; acc[1][3] += a1 * b.w;
            acc[2][0] += a2 * b.x; acc[2][1] += a2 * b.y; acc[2][2] += a2 * b.z; acc[2][3] += a2 * b.w;
            acc[3][0] += a3 * b.x; acc[3][1] += a3 * b.y; acc[3][2] += a3 * b.z; acc[3][3] += a3 * b.w;
        }
        __syncthreads();
    }
#pragma unroll
    for (int i = 0; i < 4; i++) {
        int gr2 = row0 + (ty << 2) + i;
        if (gr2 < NN) {
            *(float4*)(h1g + gr2 * HC + (tx << 2)) =
                make_float4(acc[i][0], acc[i][1], acc[i][2], acc[i][3]);
            __half2 p0 = __floats2half2_rn(acc[i][0], acc[i][1]);
            __half2 p1 = __floats2half2_rn(acc[i][2], acc[i][3]);
            *(__half2*)(h1h + gr2 * HC + (tx << 2))     = p0;
            *(__half2*)(h1h + gr2 * HC + (tx << 2) + 2) = p1;
        }
    }
}

// ---------------- node1: attention coefficients only -------------------------
__global__ void node1_kernel(const float* __restrict__ a_src, const float* __restrict__ a_dst) {
    int idx = blockIdx.x * blockDim.x + threadIdx.x;
    if (idx >= NN * NH) return;
    int h = idx & 7;
    const float4* hp = (const float4*)(h1g + idx * 8);
    float4 a = hp[0], b = hp[1];
    const float4* asp = (const float4*)(a_src + h * 8);
    const float4* adp = (const float4*)(a_dst + h * 8);
    float4 s0 = __ldg(asp), s1 = __ldg(asp + 1);
    float4 t0 = __ldg(adp), t1 = __ldg(adp + 1);
    float s = a.x * s0.x + a.y * s0.y + a.z * s0.z + a.w * s0.w +
              b.x * s1.x + b.y * s1.y + b.z * s1.z + b.w * s1.w;
    float d = a.x * t0.x + a.y * t0.y + a.z * t0.z + a.w * t0.w +
              b.x * t1.x + b.y * t1.y + b.z * t1.z + b.w * t1.w;
    s1g[idx] = s;
    d1g[idx] = d;
}

// ---------------- CSR build ---------------------------------------------------
__global__ void zero_kernel() {
    int i = blockIdx.x * blockDim.x + threadIdx.x;
    if (i < NN) cntg[i] = 0;
}

__global__ void hist_kernel(const int* __restrict__ ei) {
    int e = blockIdx.x * blockDim.x + threadIdx.x;
    if (e < NE) atomicAdd(cntg + __ldg(ei + NE + e), 1);
}

__global__ void scan_kernel() {
    __shared__ int wsum[32];
    __shared__ int carry_s;
    int t = threadIdx.x, lane = t & 31, wid = t >> 5;
    if (t == 0) carry_s = 0;
    __syncthreads();
    for (int base = 0; base < NN; base += 4096) {
        int i0 = base + t * 4;
        int v0 = (i0     < NN) ? cntg[i0]     : 0;
        int v1 = (i0 + 1 < NN) ? cntg[i0 + 1] : 0;
        int v2 = (i0 + 2 < NN) ? cntg[i0 + 2] : 0;
        int v3 = (i0 + 3 < NN) ? cntg[i0 + 3] : 0;
        int tsum = v0 + v1 + v2 + v3;
        int x = tsum;
#pragma unroll
        for (int o = 1; o < 32; o <<= 1) {
            int y = __shfl_up_sync(0xffffffffu, x, o);
            if (lane >= o) x += y;
        }
        if (lane == 31) wsum[wid] = x;
        __syncthreads();
        if (wid == 0) {
            int y = wsum[lane];
#pragma unroll
            for (int o = 1; o < 32; o <<= 1) {
                int z2 = __shfl_up_sync(0xffffffffu, y, o);
                if (lane >= o) y += z2;
            }
            wsum[lane] = y;
        }
        __syncthreads();
        int incl = x + (wid ? wsum[wid - 1] : 0);
        int excl = incl - tsum + carry_s;
        if (i0     < NN) { offg[i0]     = excl;                curg[i0]     = excl; }
        if (i0 + 1 < NN) { offg[i0 + 1] = excl + v0;           curg[i0 + 1] = excl + v0; }
        if (i0 + 2 < NN) { offg[i0 + 2] = excl + v0 + v1;      curg[i0 + 2] = excl + v0 + v1; }
        if (i0 + 3 < NN) { offg[i0 + 3] = excl + v0 + v1 + v2; curg[i0 + 3] = excl + v0 + v1 + v2; }
        __syncthreads();
        if (t == 1023) carry_s += incl;
        __syncthreads();
    }
    if (t == 0) offg[NN] = carry_s;
}

__global__ void scatter_kernel(const int* __restrict__ ei) {
    int e = blockIdx.x * blockDim.x + threadIdx.x;
    if (e >= NE) return;
    int src = __ldg(ei + e);
    int dst = __ldg(ei + NE + e);
    int pos = atomicAdd(curg + dst, 1);
    csrg[pos] = src;
}

// ---------------- agg1: warp per dst, batched weights, fused norm+bias+ELU ---
// feature role: lane l owns channels 2l,2l+1 (head l>>2)
// weight role:  lane l computes weight for edge-subgroup q=l>>3, head hw=l&7
__global__ void agg1_kernel(const float* __restrict__ b1) {
    int w = blockIdx.x * 8 + (threadIdx.x >> 5);
    if (w >= NN) return;
    int l = threadIdx.x & 31;
    int dst = w;
    int hw = l & 7, q = l >> 3;
    float dl = __ldg(d1g + dst * 8 + hw);

    // self loop: lane l computes head hw; feature role needs head l>>2 -> lane (l>>2)
    float s8 = __ldg(s1g + dst * 8 + hw);
    float w8 = __expf(lrelu(s8 + dl));
    float ww = __shfl_sync(0xffffffffu, w8, l >> 2);
    unsigned hv = __ldg((const unsigned*)h1h + dst * 32 + l);
    float2 f = __half22float2(*(__half2*)&hv);
    float a0 = ww * f.x, a1 = ww * f.y, z = ww;

    int beg = __ldg(offg + dst), end = __ldg(offg + dst + 1);
    for (int k0 = beg; k0 < end; k0 += 32) {
        int n = end - k0; if (n > 32) n = 32;
        int srcl = __ldg(csrg + k0 + (l < n ? l : n - 1));
        // phase 1: weights for 4 edges per warp-op
        float wreg[8];
#pragma unroll
        for (int g = 0; g < 8; g++) {
            if (g * 4 >= n) break;
            int e = g * 4 + q;
            int sw_ = __shfl_sync(0xffffffffu, srcl, e < n ? e : n - 1);
            wreg[g] = __expf(lrelu(__ldg(s1g + sw_ * 8 + hw) + dl));
        }
        // phase 2: feature accumulation
#pragma unroll
        for (int g = 0; g < 8; g++) {
            if (g * 4 >= n) break;
            float wq = wreg[g];
#pragma unroll
            for (int u = 0; u < 4; u++) {
                int i = g * 4 + u;
                if (i >= n) break;
                int src = __shfl_sync(0xffffffffu, srcl, i);
                float we = __shfl_sync(0xffffffffu, wq, (u << 3) + (l >> 2));
                unsigned h = __ldg((const unsigned*)h1h + src * 32 + l);
                float2 g2 = __half22float2(*(__half2*)&h);
                a0 += we * g2.x; a1 += we * g2.y; z += we;
            }
        }
    }
    float inv = 1.0f / (z + 1e-16f);
    float v0 = a0 * inv + __ldg(b1 + 2 * l);
    float v1 = a1 * inv + __ldg(b1 + 2 * l + 1);
    v0 = v0 > 0.f ? v0 : expm1f(v0);
    v1 = v1 > 0.f ? v1 : expm1f(v1);
    ((__half2*)(h1e + dst * 64))[l] = __floats2half2_rn(v0, v1);
}

// ---------------- gemm2: 4 nodes per warp, smem-staged h, W2 LDS shared ------
__global__ void gemm2_kernel(const float* __restrict__ W2, const float* __restrict__ a_s,
                             const float* __restrict__ a_d) {
    __shared__ float  Ws[64 * 44];
    __shared__ float  as_s[44], ad_s[44];
    __shared__ float2 hs[8][4][32];
    int t = threadIdx.x;
    for (int idx = t; idx < 64 * NCL; idx += 256) {
        Ws[(idx / NCL) * 44 + (idx % NCL)] = __ldg(W2 + idx);
    }
    if (t < NCL) { as_s[t] = __ldg(a_s + t); ad_s[t] = __ldg(a_d + t); }
    __syncthreads();
    int wid = t >> 5, l = t & 31;
    int base = blockIdx.x * 32 + wid * 4;
    const int lb = (l < 9) ? (32 + l) : 43;   // clamped in-bounds index for hi channels

#pragma unroll
    for (int n = 0; n < 4; n++) {
        unsigned hv = __ldg((const unsigned*)h1e + (base + n) * 32 + l);
        hs[wid][n][l] = __half22float2(*(__half2*)&hv);
    }
    __syncwarp();

    float acc0[4] = {0.f, 0.f, 0.f, 0.f};
    float acc1[4] = {0.f, 0.f, 0.f, 0.f};
#pragma unroll 8
    for (int j = 0; j < 32; j++) {
        float w0  = Ws[(2 * j) * 44 + l];
        float w1  = Ws[(2 * j + 1) * 44 + l];
        float w0b = Ws[(2 * j) * 44 + lb];
        float w1b = Ws[(2 * j + 1) * 44 + lb];
#pragma unroll
        for (int n = 0; n < 4; n++) {
            float2 p = hs[wid][n][j];
            acc0[n] += p.x * w0  + p.y * w1;
            acc1[n] += p.x * w0b + p.y * w1b;
        }
    }

#pragma unroll
    for (int n = 0; n < 4; n++) {
        int node = base + n;
        float sp = acc0[n] * as_s[l] + ((l < 9) ? acc1[n] * as_s[lb] : 0.f);
        float dp = acc0[n] * ad_s[l] + ((l < 9) ? acc1[n] * ad_s[lb] : 0.f);
#pragma unroll
        for (int o = 16; o; o >>= 1) {
            sp += __shfl_xor_sync(0xffffffffu, sp, o);
            dp += __shfl_xor_sync(0xffffffffu, dp, o);
        }
        if (l == 0) { s2g[node] = sp; d2g[node] = dp; }
        // write fp16 features: lane l<21 writes channels (2l, 2l+1)
        float x0 = __shfl_sync(0xffffffffu, acc0[n], (2 * l) & 31);
        float y0 = __shfl_sync(0xffffffffu, acc1[n], (2 * l) & 31);
        float x1 = __shfl_sync(0xffffffffu, acc0[n], (2 * l + 1) & 31);
        float y1 = __shfl_sync(0xffffffffu, acc1[n], (2 * l + 1) & 31);
        float e0 = (2 * l     < 32) ? x0 : y0;
        float e1 = (2 * l + 1 < 32) ? x1 : y1;
        if (l < 21) {
            if (l == 20) e1 = 0.f;  // channel 41 pad
            ((__half2*)(h2h + node * H2S))[l] = __floats2half2_rn(e0, e1);
        }
    }
}

// ---------------- agg2: warp per dst, batched weights, fused log_softmax -----
__global__ void agg2_kernel(const float* __restrict__ b2, float* __restrict__ out) {
    int w = blockIdx.x * 8 + (threadIdx.x >> 5);
    if (w >= NN) return;
    int l = threadIdx.x & 31;
    int dst = w;
    int li = l < 24 ? l : 23;
    float dv = __ldg(d2g + dst);

    // self loop
    float ws = __expf(lrelu(__ldg(s2g + dst) + dv));
    unsigned hv = __ldg((const unsigned*)h2h + dst * 24 + li);
    float2 f = __half22float2(*(__half2*)&hv);
    float a0 = ws * f.x, a1 = ws * f.y, z = ws;

    int beg = __ldg(offg + dst), end = __ldg(offg + dst + 1);
    for (int k0 = beg; k0 < end; k0 += 32) {
        int n = end - k0; if (n > 32) n = 32;
        int srcl = __ldg(csrg + k0 + (l < n ? l : n - 1));
        // all 32 edge weights in one warp-op
        float wall = __expf(lrelu(__ldg(s2g + srcl) + dv));
#pragma unroll 4
        for (int i = 0; i < n; i++) {
            int src  = __shfl_sync(0xffffffffu, srcl, i);
            float we = __shfl_sync(0xffffffffu, wall, i);
            unsigned h = __ldg((const unsigned*)h2h + src * 24 + li);
            float2 g = __half22float2(*(__half2*)&h);
            a0 += we * g.x; a1 += we * g.y; z += we;
        }
    }
    float inv = 1.0f / (z + 1e-16f);
    int c0 = 2 * l, c1 = 2 * l + 1;
    float v0 = (c0 < NCL) ? a0 * inv + __ldg(b2 + c0) : -1e30f;
    float v1 = (c1 < NCL) ? a1 * inv + __ldg(b2 + c1) : -1e30f;
    float m = fmaxf(v0, v1);
#pragma unroll
    for (int o = 16; o; o >>= 1) m = fmaxf(m, __shfl_xor_sync(0xffffffffu, m, o));
    float se = ((c0 < NCL) ? __expf(v0 - m) : 0.f) + ((c1 < NCL) ? __expf(v1 - m) : 0.f);
#pragma unroll
    for (int o = 16; o; o >>= 1) se += __shfl_xor_sync(0xffffffffu, se, o);
    float ls = m + logf(se);
    if (c0 < NCL) out[dst * NCL + c0] = v0 - ls;
    if (c1 < NCL) out[dst * NCL + c1] = v1 - ls;
}

// ---------------- launch ------------------------------------------------------
extern "C" void kernel_launch(void* const* d_in, const int* in_sizes, int n_in,
                              void* d_out, int out_size) {
    const float* x      = (const float*)d_in[0];
    const int*   ei     = (const int*)d_in[1];
    const float* W1     = (const float*)d_in[2];
    const float* a_src1 = (const float*)d_in[3];
    const float* a_dst1 = (const float*)d_in[4];
    const float* b1     = (const float*)d_in[5];
    const float* W2     = (const float*)d_in[6];
    const float* a_src2 = (const float*)d_in[7];
    const float* a_dst2 = (const float*)d_in[8];
    const float* b2     = (const float*)d_in[9];
    float*       out    = (float*)d_out;

    gemm1_kernel<<<(NN + 63) / 64, 256>>>(x, W1);
    node1_kernel<<<(NN * NH + 255) / 256, 256>>>(a_src1, a_dst1);

    zero_kernel<<<(NN + 255) / 256, 256>>>();
    hist_kernel<<<NE / 256, 256>>>(ei);
    scan_kernel<<<1, 1024>>>();
    scatter_kernel<<<NE / 256, 256>>>(ei);

    agg1_kernel<<<(NN + 7) / 8, 256>>>(b1);
    gemm2_kernel<<<(NN + 31) / 32, 256>>>(W2, a_src2, a_dst2);
    agg2_kernel<<<(NN + 7) / 8, 256>>>(b2, out);
}

// round 6
// speedup vs baseline: 1.6103x; 1.0932x over previous
#include <cuda_runtime.h>
#include <cuda_fp16.h>

#define NN   100000
#define NE   3200000
#define FIN  256
#define HC   64      // H1*C1
#define NH   8
#define NCL  41
#define H2S  64      // h2h row stride in halves (128B aligned rows)

// ---------------- scratch (static device globals; no runtime alloc) ----------
__device__ __align__(256) __half Wcg[FIN * 80];    // combined W1 | W1*a_src | W1*a_dst (fp16)
__device__ __align__(256) __half h1h[NN * HC];     // fp16 gemm1 out for agg1 gathers
__device__ __align__(256) __half h1e[NN * HC];     // fp16 ELU output (agg1 -> gemm2)
__device__ __align__(256) float  s1g[NN * NH];
__device__ __align__(256) float  d1g[NN * NH];
__device__ __align__(256) __half h2h[NN * H2S];    // fp16 layer2 features (ch 42..63 stay 0)
__device__ __align__(256) float  s2g[NN];
__device__ __align__(256) float  d2g[NN];
__device__ __align__(256) int    cntg[NN];
__device__ __align__(256) int    offg[NN + 1];
__device__ __align__(256) int    curg[NN];
__device__ __align__(256) int    csrg[NE];

__device__ __forceinline__ float lrelu(float x) { return fmaxf(x, 0.2f * x); }

// ---------------- prep: build combined fp16 weight matrix --------------------
// Wc[k][0..63]=W1[k][:], Wc[k][64+h]=sum_c W1[k][h*8+c]*a_src[h][c], 72+h -> a_dst
__global__ void prep_kernel(const float* __restrict__ W1, const float* __restrict__ as1,
                            const float* __restrict__ ad1) {
    int k = blockIdx.x * blockDim.x + threadIdx.x;
    if (k >= FIN) return;
    const float* row = W1 + k * 64;
    __half* out = Wcg + k * 80;
#pragma unroll
    for (int c = 0; c < 64; c++) out[c] = __float2half(row[c]);
#pragma unroll
    for (int h = 0; h < 8; h++) {
        float s = 0.f, d = 0.f;
#pragma unroll
        for (int c = 0; c < 8; c++) {
            float v = row[h * 8 + c];
            s += v * __ldg(as1 + h * 8 + c);
            d += v * __ldg(ad1 + h * 8 + c);
        }
        out[64 + h] = __float2half(s);
        out[72 + h] = __float2half(d);
    }
}

// ---------------- GEMM1 (tensor cores): [h1h | s1 | d1] = x @ Wc --------------
__device__ __forceinline__ void ldsm4(unsigned& r0, unsigned& r1, unsigned& r2, unsigned& r3,
                                      unsigned addr) {
    asm volatile("ldmatrix.sync.aligned.m8n8.x4.shared.b16 {%0,%1,%2,%3},[%4];"
                 : "=r"(r0), "=r"(r1), "=r"(r2), "=r"(r3) : "r"(addr));
}
__device__ __forceinline__ void ldsm4t(unsigned& r0, unsigned& r1, unsigned& r2, unsigned& r3,
                                       unsigned addr) {
    asm volatile("ldmatrix.sync.aligned.m8n8.x4.trans.shared.b16 {%0,%1,%2,%3},[%4];"
                 : "=r"(r0), "=r"(r1), "=r"(r2), "=r"(r3) : "r"(addr));
}
__device__ __forceinline__ void mma16816(float* c, unsigned a0, unsigned a1, unsigned a2,
                                         unsigned a3, unsigned b0, unsigned b1) {
    asm volatile("mma.sync.aligned.m16n8k16.row.col.f32.f16.f16.f32 "
                 "{%0,%1,%2,%3},{%4,%5,%6,%7},{%8,%9},{%0,%1,%2,%3};"
                 : "+f"(c[0]), "+f"(c[1]), "+f"(c[2]), "+f"(c[3])
                 : "r"(a0), "r"(a1), "r"(a2), "r"(a3), "r"(b0), "r"(b1));
}

// block: 128 rows x 80 cols, 8 warps (16 rows each), K staged in halves of 128
__global__ __launch_bounds__(256) void gemm1_tc(const float* __restrict__ x) {
    __shared__ __align__(16) __half As[128 * 24];   // row stride 24 halves (48B), pad-swizzled
    __shared__ __align__(16) __half Bs[128 * 88];   // row stride 88 halves (176B), pad-swizzled
    int t = threadIdx.x, w = t >> 5, lane = t & 31;
    int m0 = blockIdx.x * 128;

    float acc[10][4];
#pragma unroll
    for (int i = 0; i < 10; i++)
#pragma unroll
        for (int j = 0; j < 4; j++) acc[i][j] = 0.f;

    int arow = t >> 1, ac8 = (t & 1) << 3;
    int gr = m0 + arow; if (gr >= NN) gr = NN - 1;
    const float* xrow = x + (long long)gr * FIN + ac8;

    unsigned aAddrBase = (unsigned)__cvta_generic_to_shared(
        &As[((w << 4) + (lane & 15)) * 24 + ((lane >> 4) << 3)]);
    unsigned bRowOff = (lane & 15) * 88 + ((lane >> 4) << 3);

    for (int kb = 0; kb < 2; kb++) {
        __syncthreads();   // prior compute done reading Bs/As
        // stage B half (128 x 80 halves -> stride 88)
        for (int idx = t; idx < 128 * 10; idx += 256) {
            int krow = idx / 10, seg = idx % 10;
            *(uint4*)&Bs[krow * 88 + seg * 8] =
                *(const uint4*)&Wcg[(kb * 128 + krow) * 80 + seg * 8];
        }
        for (int ks = 0; ks < 8; ks++) {
            int k0 = kb * 128 + ks * 16;
            // stage A (128 x 16 halves)
            float4 v0 = __ldg((const float4*)(xrow + k0));
            float4 v1 = __ldg((const float4*)(xrow + k0 + 4));
            __half2 p0 = __floats2half2_rn(v0.x, v0.y);
            __half2 p1 = __floats2half2_rn(v0.z, v0.w);
            __half2 p2 = __floats2half2_rn(v1.x, v1.y);
            __half2 p3 = __floats2half2_rn(v1.z, v1.w);
            uint4 pk = make_uint4(*(unsigned*)&p0, *(unsigned*)&p1,
                                  *(unsigned*)&p2, *(unsigned*)&p3);
            __syncthreads();   // prior compute done reading As
            *(uint4*)&As[arow * 24 + ac8] = pk;
            __syncthreads();   // staging visible
            unsigned a0, a1, a2, a3;
            ldsm4(a0, a1, a2, a3, aAddrBase);
            unsigned bAddr0 = (unsigned)__cvta_generic_to_shared(&Bs[(ks << 4) * 88]) +
                              bRowOff * 2;
#pragma unroll
            for (int bt = 0; bt < 5; bt++) {
                unsigned b0, b1, b2, b3;
                ldsm4t(b0, b1, b2, b3, bAddr0 + bt * 32);
                mma16816(acc[bt * 2],     a0, a1, a2, a3, b0, b1);
                mma16816(acc[bt * 2 + 1], a0, a1, a2, a3, b2, b3);
            }
        }
    }

    // epilogue
    int r0 = m0 + (w << 4) + (lane >> 2);
    int r1 = r0 + 8;
    int cq = (lane & 3) << 1;
#pragma unroll
    for (int nt = 0; nt < 8; nt++) {
        int col = nt * 8 + cq;
        if (r0 < NN) *(__half2*)(h1h + r0 * 64 + col) = __floats2half2_rn(acc[nt][0], acc[nt][1]);
        if (r1 < NN) *(__half2*)(h1h + r1 * 64 + col) = __floats2half2_rn(acc[nt][2], acc[nt][3]);
    }
    if (r0 < NN) {
        s1g[r0 * 8 + cq] = acc[8][0]; s1g[r0 * 8 + cq + 1] = acc[8][1];
        d1g[r0 * 8 + cq] = acc[9][0]; d1g[r0 * 8 + cq + 1] = acc[9][1];
    }
    if (r1 < NN) {
        s1g[r1 * 8 + cq] = acc[8][2]; s1g[r1 * 8 + cq + 1] = acc[8][3];
        d1g[r1 * 8 + cq] = acc[9][2]; d1g[r1 * 8 + cq + 1] = acc[9][3];
    }
}

// ---------------- CSR build ---------------------------------------------------
__global__ void zero_kernel() {
    int i = blockIdx.x * blockDim.x + threadIdx.x;
    if (i < NN) cntg[i] = 0;
}

__global__ void hist_kernel(const int* __restrict__ ei) {
    int e = blockIdx.x * blockDim.x + threadIdx.x;
    if (e < NE) atomicAdd(cntg + __ldg(ei + NE + e), 1);
}

__global__ void scan_kernel() {
    __shared__ int wsum[32];
    __shared__ int carry_s;
    int t = threadIdx.x, lane = t & 31, wid = t >> 5;
    if (t == 0) carry_s = 0;
    __syncthreads();
    for (int base = 0; base < NN; base += 4096) {
        int i0 = base + t * 4;
        int v0 = (i0     < NN) ? cntg[i0]     : 0;
        int v1 = (i0 + 1 < NN) ? cntg[i0 + 1] : 0;
        int v2 = (i0 + 2 < NN) ? cntg[i0 + 2] : 0;
        int v3 = (i0 + 3 < NN) ? cntg[i0 + 3] : 0;
        int tsum = v0 + v1 + v2 + v3;
        int x = tsum;
#pragma unroll
        for (int o = 1; o < 32; o <<= 1) {
            int y = __shfl_up_sync(0xffffffffu, x, o);
            if (lane >= o) x += y;
        }
        if (lane == 31) wsum[wid] = x;
        __syncthreads();
        if (wid == 0) {
            int y = wsum[lane];
#pragma unroll
            for (int o = 1; o < 32; o <<= 1) {
                int z2 = __shfl_up_sync(0xffffffffu, y, o);
                if (lane >= o) y += z2;
            }
            wsum[lane] = y;
        }
        __syncthreads();
        int incl = x + (wid ? wsum[wid - 1] : 0);
        int excl = incl - tsum + carry_s;
        if (i0     < NN) { offg[i0]     = excl;                curg[i0]     = excl; }
        if (i0 + 1 < NN) { offg[i0 + 1] = excl + v0;           curg[i0 + 1] = excl + v0; }
        if (i0 + 2 < NN) { offg[i0 + 2] = excl + v0 + v1;      curg[i0 + 2] = excl + v0 + v1; }
        if (i0 + 3 < NN) { offg[i0 + 3] = excl + v0 + v1 + v2; curg[i0 + 3] = excl + v0 + v1 + v2; }
        __syncthreads();
        if (t == 1023) carry_s += incl;
        __syncthreads();
    }
    if (t == 0) offg[NN] = carry_s;
}

__global__ void scatter_kernel(const int* __restrict__ ei) {
    int e = blockIdx.x * blockDim.x + threadIdx.x;
    if (e >= NE) return;
    int src = __ldg(ei + e);
    int dst = __ldg(ei + NE + e);
    int pos = atomicAdd(curg + dst, 1);
    csrg[pos] = src;
}

// ---------------- agg1: warp per dst, batched weights, fused norm+bias+ELU ---
__global__ void agg1_kernel(const float* __restrict__ b1) {
    int w = blockIdx.x * 8 + (threadIdx.x >> 5);
    if (w >= NN) return;
    int l = threadIdx.x & 31;
    int dst = w;
    int hw = l & 7, q = l >> 3;
    float dl = __ldg(d1g + dst * 8 + hw);

    float s8 = __ldg(s1g + dst * 8 + hw);
    float w8 = __expf(lrelu(s8 + dl));
    float ww = __shfl_sync(0xffffffffu, w8, l >> 2);
    unsigned hv = __ldg((const unsigned*)h1h + dst * 32 + l);
    float2 f = __half22float2(*(__half2*)&hv);
    float a0 = ww * f.x, a1 = ww * f.y, z = ww;

    int beg = __ldg(offg + dst), end = __ldg(offg + dst + 1);
    for (int k0 = beg; k0 < end; k0 += 32) {
        int n = end - k0; if (n > 32) n = 32;
        int srcl = __ldg(csrg + k0 + (l < n ? l : n - 1));
        float wreg[8];
#pragma unroll
        for (int g = 0; g < 8; g++) {
            if (g * 4 >= n) break;
            int e = g * 4 + q;
            int sw_ = __shfl_sync(0xffffffffu, srcl, e < n ? e : n - 1);
            wreg[g] = __expf(lrelu(__ldg(s1g + sw_ * 8 + hw) + dl));
        }
#pragma unroll
        for (int g = 0; g < 8; g++) {
            if (g * 4 >= n) break;
            float wq = wreg[g];
#pragma unroll
            for (int u = 0; u < 4; u++) {
                int i = g * 4 + u;
                if (i >= n) break;
                int src = __shfl_sync(0xffffffffu, srcl, i);
                float we = __shfl_sync(0xffffffffu, wq, (u << 3) + (l >> 2));
                unsigned h = __ldg((const unsigned*)h1h + src * 32 + l);
                float2 g2 = __half22float2(*(__half2*)&h);
                a0 += we * g2.x; a1 += we * g2.y; z += we;
            }
        }
    }
    float inv = 1.0f / (z + 1e-16f);
    float v0 = a0 * inv + __ldg(b1 + 2 * l);
    float v1 = a1 * inv + __ldg(b1 + 2 * l + 1);
    v0 = v0 > 0.f ? v0 : expm1f(v0);
    v1 = v1 > 0.f ? v1 : expm1f(v1);
    ((__half2*)(h1e + dst * 64))[l] = __floats2half2_rn(v0, v1);
}

// ---------------- gemm2: 4 nodes per warp, smem-staged h, W2 LDS shared ------
__global__ void gemm2_kernel(const float* __restrict__ W2, const float* __restrict__ a_s,
                             const float* __restrict__ a_d) {
    __shared__ float  Ws[64 * 44];
    __shared__ float  as_s[44], ad_s[44];
    __shared__ float2 hs[8][4][32];
    int t = threadIdx.x;
    for (int idx = t; idx < 64 * NCL; idx += 256) {
        Ws[(idx / NCL) * 44 + (idx % NCL)] = __ldg(W2 + idx);
    }
    if (t < NCL) { as_s[t] = __ldg(a_s + t); ad_s[t] = __ldg(a_d + t); }
    __syncthreads();
    int wid = t >> 5, l = t & 31;
    int base = blockIdx.x * 32 + wid * 4;
    const int lb = (l < 9) ? (32 + l) : 43;

#pragma unroll
    for (int n = 0; n < 4; n++) {
        unsigned hv = __ldg((const unsigned*)h1e + (base + n) * 32 + l);
        hs[wid][n][l] = __half22float2(*(__half2*)&hv);
    }
    __syncwarp();

    float acc0[4] = {0.f, 0.f, 0.f, 0.f};
    float acc1[4] = {0.f, 0.f, 0.f, 0.f};
#pragma unroll 8
    for (int j = 0; j < 32; j++) {
        float w0  = Ws[(2 * j) * 44 + l];
        float w1  = Ws[(2 * j + 1) * 44 + l];
        float w0b = Ws[(2 * j) * 44 + lb];
        float w1b = Ws[(2 * j + 1) * 44 + lb];
#pragma unroll
        for (int n = 0; n < 4; n++) {
            float2 p = hs[wid][n][j];
            acc0[n] += p.x * w0  + p.y * w1;
            acc1[n] += p.x * w0b + p.y * w1b;
        }
    }

#pragma unroll
    for (int n = 0; n < 4; n++) {
        int node = base + n;
        float sp = acc0[n] * as_s[l] + ((l < 9) ? acc1[n] * as_s[lb] : 0.f);
        float dp = acc0[n] * ad_s[l] + ((l < 9) ? acc1[n] * ad_s[lb] : 0.f);
#pragma unroll
        for (int o = 16; o; o >>= 1) {
            sp += __shfl_xor_sync(0xffffffffu, sp, o);
            dp += __shfl_xor_sync(0xffffffffu, dp, o);
        }
        if (l == 0) { s2g[node] = sp; d2g[node] = dp; }
        float x0 = __shfl_sync(0xffffffffu, acc0[n], (2 * l) & 31);
        float y0 = __shfl_sync(0xffffffffu, acc1[n], (2 * l) & 31);
        float x1 = __shfl_sync(0xffffffffu, acc0[n], (2 * l + 1) & 31);
        float y1 = __shfl_sync(0xffffffffu, acc1[n], (2 * l + 1) & 31);
        float e0 = (2 * l     < 32) ? x0 : y0;
        float e1 = (2 * l + 1 < 32) ? x1 : y1;
        if (l < 21) {
            if (l == 20) e1 = 0.f;  // channel 41 pad
            ((__half2*)(h2h + node * H2S))[l] = __floats2half2_rn(e0, e1);
        }
    }
}

// ---------------- agg2: warp per dst, batched weights, fused log_softmax -----
__global__ void agg2_kernel(const float* __restrict__ b2, float* __restrict__ out) {
    int w = blockIdx.x * 8 + (threadIdx.x >> 5);
    if (w >= NN) return;
    int l = threadIdx.x & 31;
    int dst = w;
    int li = l < 24 ? l : 23;
    float dv = __ldg(d2g + dst);

    float ws = __expf(lrelu(__ldg(s2g + dst) + dv));
    unsigned hv = __ldg((const unsigned*)h2h + dst * 32 + li);
    float2 f = __half22float2(*(__half2*)&hv);
    float a0 = ws * f.x, a1 = ws * f.y, z = ws;

    int beg = __ldg(offg + dst), end = __ldg(offg + dst + 1);
    for (int k0 = beg; k0 < end; k0 += 32) {
        int n = end - k0; if (n > 32) n = 32;
        int srcl = __ldg(csrg + k0 + (l < n ? l : n - 1));
        float wall = __expf(lrelu(__ldg(s2g + srcl) + dv));
#pragma unroll 4
        for (int i = 0; i < n; i++) {
            int src  = __shfl_sync(0xffffffffu, srcl, i);
            float we = __shfl_sync(0xffffffffu, wall, i);
            unsigned h = __ldg((const unsigned*)h2h + src * 32 + li);
            float2 g = __half22float2(*(__half2*)&h);
            a0 += we * g.x; a1 += we * g.y; z += we;
        }
    }
    float inv = 1.0f / (z + 1e-16f);
    int c0 = 2 * l, c1 = 2 * l + 1;
    float v0 = (c0 < NCL) ? a0 * inv + __ldg(b2 + c0) : -1e30f;
    float v1 = (c1 < NCL) ? a1 * inv + __ldg(b2 + c1) : -1e30f;
    float m = fmaxf(v0, v1);
#pragma unroll
    for (int o = 16; o; o >>= 1) m = fmaxf(m, __shfl_xor_sync(0xffffffffu, m, o));
    float se = ((c0 < NCL) ? __expf(v0 - m) : 0.f) + ((c1 < NCL) ? __expf(v1 - m) : 0.f);
#pragma unroll
    for (int o = 16; o; o >>= 1) se += __shfl_xor_sync(0xffffffffu, se, o);
    float ls = m + logf(se);
    if (c0 < NCL) out[dst * NCL + c0] = v0 - ls;
    if (c1 < NCL) out[dst * NCL + c1] = v1 - ls;
}

// ---------------- launch ------------------------------------------------------
extern "C" void kernel_launch(void* const* d_in, const int* in_sizes, int n_in,
                              void* d_out, int out_size) {
    const float* x      = (const float*)d_in[0];
    const int*   ei     = (const int*)d_in[1];
    const float* W1     = (const float*)d_in[2];
    const float* a_src1 = (const float*)d_in[3];
    const float* a_dst1 = (const float*)d_in[4];
    const float* b1     = (const float*)d_in[5];
    const float* W2     = (const float*)d_in[6];
    const float* a_src2 = (const float*)d_in[7];
    const float* a_dst2 = (const float*)d_in[8];
    const float* b2     = (const float*)d_in[9];
    float*       out    = (float*)d_out;

    prep_kernel<<<1, 256>>>(W1, a_src1, a_dst1);
    gemm1_tc<<<(NN + 127) / 128, 256>>>(x);

    zero_kernel<<<(NN + 255) / 256, 256>>>();
    hist_kernel<<<NE / 256, 256>>>(ei);
    scan_kernel<<<1, 1024>>>();
    scatter_kernel<<<NE / 256, 256>>>(ei);

    agg1_kernel<<<(NN + 7) / 8, 256>>>(b1);
    gemm2_kernel<<<(NN + 31) / 32, 256>>>(W2, a_src2, a_dst2);
    agg2_kernel<<<(NN + 7) / 8, 256>>>(b2, out);
}

// round 7
// speedup vs baseline: 1.8105x; 1.1243x over previous
#include <cuda_runtime.h>
#include <cuda_fp16.h>

#define NN   100000
#define NE   3200000
#define FIN  256
#define HC   64      // H1*C1
#define NH   8
#define NCL  41
#define H2S  64      // h2h row stride in halves (128B aligned rows)

// ---------------- scratch (static device globals; no runtime alloc) ----------
__device__ __align__(256) __half Wcg[FIN * 80];    // combined W1 | W1*a_src | W1*a_dst (fp16)
__device__ __align__(256) __half h1h[NN * HC];     // fp16 gemm1 out for agg1 gathers
__device__ __align__(256) __half h1e[NN * HC];     // fp16 ELU output (agg1 -> gemm2)
__device__ __align__(256) float  s1g[NN * NH];
__device__ __align__(256) float  d1g[NN * NH];
__device__ __align__(256) __half h2h[NN * H2S];    // fp16 layer2 features (ch 42..63 stay 0)
__device__ __align__(256) float  s2g[NN];
__device__ __align__(256) float  d2g[NN];
__device__ __align__(256) int    cntg[NN];
__device__ __align__(256) int    offg[NN + 1];
__device__ __align__(256) int    rankg[NE];
__device__ __align__(256) int    csrg[NE];
__device__ __align__(256) int    bsumg[128];

__device__ __forceinline__ float lrelu(float x) { return fmaxf(x, 0.2f * x); }

// ---------------- prep: build combined fp16 weight matrix --------------------
__global__ void prep_kernel(const float* __restrict__ W1, const float* __restrict__ as1,
                            const float* __restrict__ ad1) {
    int k = blockIdx.x * blockDim.x + threadIdx.x;
    if (k >= FIN) return;
    const float* row = W1 + k * 64;
    __half* out = Wcg + k * 80;
#pragma unroll
    for (int c = 0; c < 64; c++) out[c] = __float2half(row[c]);
#pragma unroll
    for (int h = 0; h < 8; h++) {
        float s = 0.f, d = 0.f;
#pragma unroll
        for (int c = 0; c < 8; c++) {
            float v = row[h * 8 + c];
            s += v * __ldg(as1 + h * 8 + c);
            d += v * __ldg(ad1 + h * 8 + c);
        }
        out[64 + h] = __float2half(s);
        out[72 + h] = __float2half(d);
    }
}

// ---------------- GEMM1 (tensor cores): [h1h | s1 | d1] = x @ Wc --------------
__device__ __forceinline__ void ldsm4(unsigned& r0, unsigned& r1, unsigned& r2, unsigned& r3,
                                      unsigned addr) {
    asm volatile("ldmatrix.sync.aligned.m8n8.x4.shared.b16 {%0,%1,%2,%3},[%4];"
                 : "=r"(r0), "=r"(r1), "=r"(r2), "=r"(r3) : "r"(addr));
}
__device__ __forceinline__ void ldsm4t(unsigned& r0, unsigned& r1, unsigned& r2, unsigned& r3,
                                       unsigned addr) {
    asm volatile("ldmatrix.sync.aligned.m8n8.x4.trans.shared.b16 {%0,%1,%2,%3},[%4];"
                 : "=r"(r0), "=r"(r1), "=r"(r2), "=r"(r3) : "r"(addr));
}
__device__ __forceinline__ void mma16816(float* c, unsigned a0, unsigned a1, unsigned a2,
                                         unsigned a3, unsigned b0, unsigned b1) {
    asm volatile("mma.sync.aligned.m16n8k16.row.col.f32.f16.f16.f32 "
                 "{%0,%1,%2,%3},{%4,%5,%6,%7},{%8,%9},{%0,%1,%2,%3};"
                 : "+f"(c[0]), "+f"(c[1]), "+f"(c[2]), "+f"(c[3])
                 : "r"(a0), "r"(a1), "r"(a2), "r"(a3), "r"(b0), "r"(b1));
}

// block: 128 rows x 80 cols; A staged in 64-K chunks (few syncthreads)
__global__ __launch_bounds__(256) void gemm1_tc(const float* __restrict__ x) {
    __shared__ __align__(16) __half As[128 * 72];   // 128 rows x (64 K + 8 pad)
    __shared__ __align__(16) __half Bs[128 * 88];   // 128 K x (80 cols + 8 pad)
    int t = threadIdx.x, w = t >> 5, lane = t & 31;
    int m0 = blockIdx.x * 128;

    float acc[10][4];
#pragma unroll
    for (int i = 0; i < 10; i++)
#pragma unroll
        for (int j = 0; j < 4; j++) acc[i][j] = 0.f;

    int arow = t >> 1;                 // 0..127
    int ac32 = (t & 1) << 5;           // 0 or 32
    int gr = m0 + arow; if (gr >= NN) gr = NN - 1;
    const float* xrow = x + (long long)gr * FIN;

    unsigned aBase = (unsigned)__cvta_generic_to_shared(
        &As[((w << 4) + (lane & 15)) * 72 + ((lane >> 4) << 3)]);
    unsigned bRowOff = ((lane & 15) * 88 + ((lane >> 4) << 3)) * 2;

    for (int kb = 0; kb < 2; kb++) {
        __syncthreads();   // prior reads of Bs complete
        for (int idx = t; idx < 128 * 10; idx += 256) {
            int krow = idx / 10, seg = idx % 10;
            *(uint4*)&Bs[krow * 88 + seg * 8] =
                *(const uint4*)&Wcg[(kb * 128 + krow) * 80 + seg * 8];
        }
        for (int c = 0; c < 2; c++) {
            __syncthreads();   // prior A reads done; (c==0) Bs visible
            int kc = kb * 128 + c * 64 + ac32;
            uint4 pk[4];
#pragma unroll
            for (int q = 0; q < 4; q++) {
                float4 v0 = __ldg((const float4*)(xrow + kc + q * 8));
                float4 v1 = __ldg((const float4*)(xrow + kc + q * 8 + 4));
                __half2 p0 = __floats2half2_rn(v0.x, v0.y);
                __half2 p1 = __floats2half2_rn(v0.z, v0.w);
                __half2 p2 = __floats2half2_rn(v1.x, v1.y);
                __half2 p3 = __floats2half2_rn(v1.z, v1.w);
                pk[q] = make_uint4(*(unsigned*)&p0, *(unsigned*)&p1,
                                   *(unsigned*)&p2, *(unsigned*)&p3);
            }
#pragma unroll
            for (int q = 0; q < 4; q++)
                *(uint4*)&As[arow * 72 + ac32 + q * 8] = pk[q];
            __syncthreads();   // A chunk visible
#pragma unroll
            for (int ks = 0; ks < 4; ks++) {
                unsigned a0, a1, a2, a3;
                ldsm4(a0, a1, a2, a3, aBase + ks * 32);
                unsigned bAddr = (unsigned)__cvta_generic_to_shared(
                                     &Bs[(c * 64 + ks * 16) * 88]) + bRowOff;
#pragma unroll
                for (int bt = 0; bt < 5; bt++) {
                    unsigned b0, b1, b2, b3;
                    ldsm4t(b0, b1, b2, b3, bAddr + bt * 32);
                    mma16816(acc[bt * 2],     a0, a1, a2, a3, b0, b1);
                    mma16816(acc[bt * 2 + 1], a0, a1, a2, a3, b2, b3);
                }
            }
        }
    }

    int r0 = m0 + (w << 4) + (lane >> 2);
    int r1 = r0 + 8;
    int cq = (lane & 3) << 1;
#pragma unroll
    for (int nt = 0; nt < 8; nt++) {
        int col = nt * 8 + cq;
        if (r0 < NN) *(__half2*)(h1h + r0 * 64 + col) = __floats2half2_rn(acc[nt][0], acc[nt][1]);
        if (r1 < NN) *(__half2*)(h1h + r1 * 64 + col) = __floats2half2_rn(acc[nt][2], acc[nt][3]);
    }
    if (r0 < NN) {
        s1g[r0 * 8 + cq] = acc[8][0]; s1g[r0 * 8 + cq + 1] = acc[8][1];
        d1g[r0 * 8 + cq] = acc[9][0]; d1g[r0 * 8 + cq + 1] = acc[9][1];
    }
    if (r1 < NN) {
        s1g[r1 * 8 + cq] = acc[8][2]; s1g[r1 * 8 + cq + 1] = acc[8][3];
        d1g[r1 * 8 + cq] = acc[9][2]; d1g[r1 * 8 + cq + 1] = acc[9][3];
    }
}

// ---------------- CSR build ---------------------------------------------------
__global__ void zero_kernel() {
    int i = blockIdx.x * blockDim.x + threadIdx.x;
    if (i < NN) cntg[i] = 0;
}

// histogram + per-edge rank (atomicAdd return value)
__global__ void hist_kernel(const int* __restrict__ ei) {
    int e = blockIdx.x * blockDim.x + threadIdx.x;
    if (e < NE) rankg[e] = atomicAdd(cntg + __ldg(ei + NE + e), 1);
}

// scan1: per-block (1024) exclusive scan of cntg -> offg, block sums -> bsumg
__global__ void scan1_kernel() {
    __shared__ int wsum[32];
    int t = threadIdx.x, lane = t & 31, wd = t >> 5;
    int i = blockIdx.x * 1024 + t;
    int v = (i < NN) ? cntg[i] : 0;
    int x = v;
#pragma unroll
    for (int o = 1; o < 32; o <<= 1) {
        int y = __shfl_up_sync(0xffffffffu, x, o);
        if (lane >= o) x += y;
    }
    if (lane == 31) wsum[wd] = x;
    __syncthreads();
    if (wd == 0) {
        int y = wsum[lane];
#pragma unroll
        for (int o = 1; o < 32; o <<= 1) {
            int z = __shfl_up_sync(0xffffffffu, y, o);
            if (lane >= o) y += z;
        }
        wsum[lane] = y;
    }
    __syncthreads();
    int excl = x - v + (wd ? wsum[wd - 1] : 0);
    if (i < NN) offg[i] = excl;
    if (t == 1023) bsumg[blockIdx.x] = excl + v;
}

// scan2: 1 block (128 thr) exclusive scan of 98 block sums (in place)
__global__ void scan2_kernel() {
    __shared__ int ws[4];
    int t = threadIdx.x, lane = t & 31, wd = t >> 5;
    int v = (t < 98) ? bsumg[t] : 0;
    int x = v;
#pragma unroll
    for (int o = 1; o < 32; o <<= 1) {
        int y = __shfl_up_sync(0xffffffffu, x, o);
        if (lane >= o) x += y;
    }
    if (lane == 31) ws[wd] = x;
    __syncthreads();
    int add = 0;
    for (int k = 0; k < wd; k++) add += ws[k];
    int excl = x - v + add;
    if (t < 98) bsumg[t] = excl;
    if (t == 127) offg[NN] = excl + v;   // grand total (v=0 here)
}

// scan3: add block offsets
__global__ void scan3_kernel() {
    int i = blockIdx.x * 1024 + threadIdx.x;
    if (i < NN) offg[i] += bsumg[blockIdx.x];
}

// scatter without atomics, using precomputed ranks
__global__ void scatter_kernel(const int* __restrict__ ei) {
    int e = blockIdx.x * blockDim.x + threadIdx.x;
    if (e >= NE) return;
    int src = __ldg(ei + e);
    int dst = __ldg(ei + NE + e);
    csrg[__ldg(offg + dst) + rankg[e]] = src;
}

// ---------------- agg1: warp per dst, batched weights, fused norm+bias+ELU ---
__global__ void agg1_kernel(const float* __restrict__ b1) {
    int w = blockIdx.x * 8 + (threadIdx.x >> 5);
    if (w >= NN) return;
    int l = threadIdx.x & 31;
    int dst = w;
    int hw = l & 7, q = l >> 3;
    float dl = __ldg(d1g + dst * 8 + hw);

    float s8 = __ldg(s1g + dst * 8 + hw);
    float w8 = __expf(lrelu(s8 + dl));
    float ww = __shfl_sync(0xffffffffu, w8, l >> 2);
    unsigned hv = __ldg((const unsigned*)h1h + dst * 32 + l);
    float2 f = __half22float2(*(__half2*)&hv);
    float a0 = ww * f.x, a1 = ww * f.y, z = ww;

    int beg = __ldg(offg + dst), end = __ldg(offg + dst + 1);
    for (int k0 = beg; k0 < end; k0 += 32) {
        int n = end - k0; if (n > 32) n = 32;
        int srcl = __ldg(csrg + k0 + (l < n ? l : n - 1));
        float wreg[8];
#pragma unroll
        for (int g = 0; g < 8; g++) {
            if (g * 4 >= n) break;
            int e = g * 4 + q;
            int sw_ = __shfl_sync(0xffffffffu, srcl, e < n ? e : n - 1);
            wreg[g] = __expf(lrelu(__ldg(s1g + sw_ * 8 + hw) + dl));
        }
#pragma unroll
        for (int g = 0; g < 8; g++) {
            if (g * 4 >= n) break;
            float wq = wreg[g];
#pragma unroll
            for (int u = 0; u < 4; u++) {
                int i = g * 4 + u;
                if (i >= n) break;
                int src = __shfl_sync(0xffffffffu, srcl, i);
                float we = __shfl_sync(0xffffffffu, wq, (u << 3) + (l >> 2));
                unsigned h = __ldg((const unsigned*)h1h + src * 32 + l);
                float2 g2 = __half22float2(*(__half2*)&h);
                a0 += we * g2.x; a1 += we * g2.y; z += we;
            }
        }
    }
    float inv = 1.0f / (z + 1e-16f);
    float v0 = a0 * inv + __ldg(b1 + 2 * l);
    float v1 = a1 * inv + __ldg(b1 + 2 * l + 1);
    v0 = v0 > 0.f ? v0 : expm1f(v0);
    v1 = v1 > 0.f ? v1 : expm1f(v1);
    ((__half2*)(h1e + dst * 64))[l] = __floats2half2_rn(v0, v1);
}

// ---------------- gemm2: 4 nodes per warp, smem-staged h, W2 LDS shared ------
__global__ void gemm2_kernel(const float* __restrict__ W2, const float* __restrict__ a_s,
                             const float* __restrict__ a_d) {
    __shared__ float  Ws[64 * 44];
    __shared__ float  as_s[44], ad_s[44];
    __shared__ float2 hs[8][4][32];
    int t = threadIdx.x;
    for (int idx = t; idx < 64 * NCL; idx += 256) {
        Ws[(idx / NCL) * 44 + (idx % NCL)] = __ldg(W2 + idx);
    }
    if (t < NCL) { as_s[t] = __ldg(a_s + t); ad_s[t] = __ldg(a_d + t); }
    __syncthreads();
    int wid = t >> 5, l = t & 31;
    int base = blockIdx.x * 32 + wid * 4;
    const int lb = (l < 9) ? (32 + l) : 43;

#pragma unroll
    for (int n = 0; n < 4; n++) {
        unsigned hv = __ldg((const unsigned*)h1e + (base + n) * 32 + l);
        hs[wid][n][l] = __half22float2(*(__half2*)&hv);
    }
    __syncwarp();

    float acc0[4] = {0.f, 0.f, 0.f, 0.f};
    float acc1[4] = {0.f, 0.f, 0.f, 0.f};
#pragma unroll 8
    for (int j = 0; j < 32; j++) {
        float w0  = Ws[(2 * j) * 44 + l];
        float w1  = Ws[(2 * j + 1) * 44 + l];
        float w0b = Ws[(2 * j) * 44 + lb];
        float w1b = Ws[(2 * j + 1) * 44 + lb];
#pragma unroll
        for (int n = 0; n < 4; n++) {
            float2 p = hs[wid][n][j];
            acc0[n] += p.x * w0  + p.y * w1;
            acc1[n] += p.x * w0b + p.y * w1b;
        }
    }

#pragma unroll
    for (int n = 0; n < 4; n++) {
        int node = base + n;
        float sp = acc0[n] * as_s[l] + ((l < 9) ? acc1[n] * as_s[lb] : 0.f);
        float dp = acc0[n] * ad_s[l] + ((l < 9) ? acc1[n] * ad_s[lb] : 0.f);
#pragma unroll
        for (int o = 16; o; o >>= 1) {
            sp += __shfl_xor_sync(0xffffffffu, sp, o);
            dp += __shfl_xor_sync(0xffffffffu, dp, o);
        }
        if (l == 0) { s2g[node] = sp; d2g[node] = dp; }
        float x0 = __shfl_sync(0xffffffffu, acc0[n], (2 * l) & 31);
        float y0 = __shfl_sync(0xffffffffu, acc1[n], (2 * l) & 31);
        float x1 = __shfl_sync(0xffffffffu, acc0[n], (2 * l + 1) & 31);
        float y1 = __shfl_sync(0xffffffffu, acc1[n], (2 * l + 1) & 31);
        float e0 = (2 * l     < 32) ? x0 : y0;
        float e1 = (2 * l + 1 < 32) ? x1 : y1;
        if (l < 21) {
            if (l == 20) e1 = 0.f;  // channel 41 pad
            ((__half2*)(h2h + node * H2S))[l] = __floats2half2_rn(e0, e1);
        }
    }
}

// ---------------- agg2: warp per dst, batched weights, fused log_softmax -----
__global__ void agg2_kernel(const float* __restrict__ b2, float* __restrict__ out) {
    int w = blockIdx.x * 8 + (threadIdx.x >> 5);
    if (w >= NN) return;
    int l = threadIdx.x & 31;
    int dst = w;
    int li = l < 24 ? l : 23;
    float dv = __ldg(d2g + dst);

    float ws = __expf(lrelu(__ldg(s2g + dst) + dv));
    unsigned hv = __ldg((const unsigned*)h2h + dst * 32 + li);
    float2 f = __half22float2(*(__half2*)&hv);
    float a0 = ws * f.x, a1 = ws * f.y, z = ws;

    int beg = __ldg(offg + dst), end = __ldg(offg + dst + 1);
    for (int k0 = beg; k0 < end; k0 += 32) {
        int n = end - k0; if (n > 32) n = 32;
        int srcl = __ldg(csrg + k0 + (l < n ? l : n - 1));
        float wall = __expf(lrelu(__ldg(s2g + srcl) + dv));
#pragma unroll 4
        for (int i = 0; i < n; i++) {
            int src  = __shfl_sync(0xffffffffu, srcl, i);
            float we = __shfl_sync(0xffffffffu, wall, i);
            unsigned h = __ldg((const unsigned*)h2h + src * 32 + li);
            float2 g = __half22float2(*(__half2*)&h);
            a0 += we * g.x; a1 += we * g.y; z += we;
        }
    }
    float inv = 1.0f / (z + 1e-16f);
    int c0 = 2 * l, c1 = 2 * l + 1;
    float v0 = (c0 < NCL) ? a0 * inv + __ldg(b2 + c0) : -1e30f;
    float v1 = (c1 < NCL) ? a1 * inv + __ldg(b2 + c1) : -1e30f;
    float m = fmaxf(v0, v1);
#pragma unroll
    for (int o = 16; o; o >>= 1) m = fmaxf(m, __shfl_xor_sync(0xffffffffu, m, o));
    float se = ((c0 < NCL) ? __expf(v0 - m) : 0.f) + ((c1 < NCL) ? __expf(v1 - m) : 0.f);
#pragma unroll
    for (int o = 16; o; o >>= 1) se += __shfl_xor_sync(0xffffffffu, se, o);
    float ls = m + logf(se);
    if (c0 < NCL) out[dst * NCL + c0] = v0 - ls;
    if (c1 < NCL) out[dst * NCL + c1] = v1 - ls;
}

// ---------------- launch ------------------------------------------------------
extern "C" void kernel_launch(void* const* d_in, const int* in_sizes, int n_in,
                              void* d_out, int out_size) {
    const float* x      = (const float*)d_in[0];
    const int*   ei     = (const int*)d_in[1];
    const float* W1     = (const float*)d_in[2];
    const float* a_src1 = (const float*)d_in[3];
    const float* a_dst1 = (const float*)d_in[4];
    const float* b1     = (const float*)d_in[5];
    const float* W2     = (const float*)d_in[6];
    const float* a_src2 = (const float*)d_in[7];
    const float* a_dst2 = (const float*)d_in[8];
    const float* b2     = (const float*)d_in[9];
    float*       out    = (float*)d_out;

    // one-time infra (created on first, uncaptured call)
    static cudaStream_t s2 = nullptr;
    static cudaEvent_t  evA = nullptr, evB = nullptr;
    if (!s2) {
        cudaStreamCreateWithFlags(&s2, cudaStreamNonBlocking);
        cudaEventCreateWithFlags(&evA, cudaEventDisableTiming);
        cudaEventCreateWithFlags(&evB, cudaEventDisableTiming);
    }

    // fork: GEMM1 chain on s2, CSR chain on main stream
    cudaEventRecord(evA, 0);
    cudaStreamWaitEvent(s2, evA, 0);
    prep_kernel<<<1, 256, 0, s2>>>(W1, a_src1, a_dst1);
    gemm1_tc<<<(NN + 127) / 128, 256, 0, s2>>>(x);
    cudaEventRecord(evB, s2);

    zero_kernel<<<(NN + 255) / 256, 256>>>();
    hist_kernel<<<NE / 256, 256>>>(ei);
    scan1_kernel<<<(NN + 1023) / 1024, 1024>>>();
    scan2_kernel<<<1, 128>>>();
    scan3_kernel<<<(NN + 1023) / 1024, 1024>>>();
    scatter_kernel<<<NE / 256, 256>>>(ei);

    cudaStreamWaitEvent(0, evB, 0);   // join
    agg1_kernel<<<(NN + 7) / 8, 256>>>(b1);
    gemm2_kernel<<<(NN + 31) / 32, 256>>>(W2, a_src2, a_dst2);
    agg2_kernel<<<(NN + 7) / 8, 256>>>(b2, out);
}